// round 15
// baseline (speedup 1.0000x reference)
#include <cuda_runtime.h>
#include <cuda_bf16.h>
#include <cuda_fp16.h>
#include <cstdint>

#define TT 1024
#define DM 512
#define NB 4
#define NH 8
#define DK 64
#define LL 2047   // 2*T - 1
#define RSTR 2048
typedef long long ll;
typedef unsigned long long u64;

// ---------------- scratch ----------------
__device__ float g_QKV[3LL * NB * TT * DM];     // Q | (K,V unused)
__device__ __half g_Rh[32LL * 512 * RSTR];      // R in fp16
__device__ unsigned int g_Mb[NB * TT * 32];
__device__ unsigned int g_Kph[32LL * 1024 * 32];
__device__ unsigned int g_Kpl[32LL * 1024 * 32];
__device__ unsigned int g_VTh[32LL * 64 * 512];   // fp16x2 pairs along s
__device__ unsigned int g_xph[NB * TT * 256],  g_xpl[NB * TT * 256];
__device__ unsigned int g_pph[2047 * 256],     g_ppl[2047 * 256];
__device__ unsigned int g_Wqkvh[3 * 256 * 512], g_Wqkvl[3 * 256 * 512];
__device__ unsigned int g_Wph[256 * 512], g_Wpl[256 * 512];
__device__ unsigned int g_Woh[256 * 512], g_Wol[256 * 512];
__device__ unsigned int g_Pph[2047 * 256];            // single fp16 pairs
__device__ unsigned int g_QRh[32LL * 512 * 32], g_QRl[32LL * 512 * 32];  // fp16 hi/lo
__device__ unsigned int g_Oph[NB * TT * 256], g_Opl[NB * TT * 256];

// ---------------- helpers ----------------
__device__ __forceinline__ float bf16_hi(float x) {
    return __bfloat162float(__float2bfloat16(x));
}
__device__ __forceinline__ uint32_t pack_bf16(float lo_elem, float hi_elem) {
    uint32_t r;
    asm("cvt.rn.bf16x2.f32 %0, %1, %2;" : "=r"(r) : "f"(hi_elem), "f"(lo_elem));
    return r;
}
__device__ __forceinline__ void split_pack(float a, float b, uint32_t& ph, uint32_t& pl) {
    float ha = bf16_hi(a), hb = bf16_hi(b);
    ph = pack_bf16(a, b);
    pl = pack_bf16(a - ha, b - hb);
}
__device__ __forceinline__ float f16_hi(float x) {
    return __half2float(__float2half_rn(x));
}
__device__ __forceinline__ uint32_t pack_f16(float lo_elem, float hi_elem) {
    uint32_t r;
    asm("cvt.rn.f16x2.f32 %0, %1, %2;" : "=r"(r) : "f"(hi_elem), "f"(lo_elem));
    return r;
}
__device__ __forceinline__ void split_pack_f16(float a, float b, uint32_t& ph, uint32_t& pl) {
    float ha = f16_hi(a), hb = f16_hi(b);
    ph = pack_f16(a, b);
    pl = pack_f16(a - ha, b - hb);
}
__device__ __forceinline__ void mma_bf16(float* d, const uint32_t* a, uint32_t b0, uint32_t b1) {
    asm volatile(
        "mma.sync.aligned.m16n8k16.row.col.f32.bf16.bf16.f32 "
        "{%0,%1,%2,%3}, {%4,%5,%6,%7}, {%8,%9}, {%0,%1,%2,%3};\n"
        : "+f"(d[0]), "+f"(d[1]), "+f"(d[2]), "+f"(d[3])
        : "r"(a[0]), "r"(a[1]), "r"(a[2]), "r"(a[3]), "r"(b0), "r"(b1));
}
__device__ __forceinline__ void mma_f16(float* d, const uint32_t* a, uint32_t b0, uint32_t b1) {
    asm volatile(
        "mma.sync.aligned.m16n8k16.row.col.f32.f16.f16.f32 "
        "{%0,%1,%2,%3}, {%4,%5,%6,%7}, {%8,%9}, {%0,%1,%2,%3};\n"
        : "+f"(d[0]), "+f"(d[1]), "+f"(d[2]), "+f"(d[3])
        : "r"(a[0]), "r"(a[1]), "r"(a[2]), "r"(a[3]), "r"(b0), "r"(b1));
}
__device__ __forceinline__ void ldsm_x4(uint32_t& r0, uint32_t& r1, uint32_t& r2, uint32_t& r3,
                                        uint32_t addr) {
    asm volatile("ldmatrix.sync.aligned.m8n8.x4.shared.b16 {%0,%1,%2,%3}, [%4];\n"
                 : "=r"(r0), "=r"(r1), "=r"(r2), "=r"(r3) : "r"(addr));
}
__device__ __forceinline__ void ldsm_x2(uint32_t& r0, uint32_t& r1, uint32_t addr) {
    asm volatile("ldmatrix.sync.aligned.m8n8.x2.shared.b16 {%0,%1}, [%2];\n"
                 : "=r"(r0), "=r"(r1) : "r"(addr));
}
__device__ __forceinline__ void cp_async16(uint32_t dst, const void* src, bool p) {
    asm volatile("cp.async.cg.shared.global [%0], [%1], 16, %2;\n"
                 :: "r"(dst), "l"(src), "r"(p ? 16 : 0));
}
__device__ __forceinline__ void cp_commit() { asm volatile("cp.async.commit_group;\n"); }
template <int N>
__device__ __forceinline__ void cp_wait() { asm volatile("cp.async.wait_group %0;\n" :: "n"(N)); }

// ---------------- mega-pack 1: all input-only packs, grid (4096,1,8) ----------------
__global__ void __launch_bounds__(256) megapack1(
    const float* __restrict__ x, const float* __restrict__ pos,
    const unsigned char* __restrict__ mask,
    const float* __restrict__ Wq, const float* __restrict__ Wk,
    const float* __restrict__ Wv, const float* __restrict__ Wp,
    const float* __restrict__ Wo,
    unsigned int* __restrict__ Wqkvh, unsigned int* __restrict__ Wqkvl,
    unsigned int* __restrict__ Wph, unsigned int* __restrict__ Wpl,
    unsigned int* __restrict__ Woh, unsigned int* __restrict__ Wol,
    unsigned int* __restrict__ xph, unsigned int* __restrict__ xpl,
    unsigned int* __restrict__ pph, unsigned int* __restrict__ ppl,
    unsigned int* __restrict__ Mb)
{
    const int zz = blockIdx.z, bx = blockIdx.x, tid = threadIdx.x;
    if (zz < 5) {
        if (bx >= 512) return;
        int i = bx * 256 + tid;
        int r = i >> 9, n = i & 511;
        const float* W = zz == 0 ? Wq : zz == 1 ? Wk : zz == 2 ? Wv : zz == 3 ? Wp : Wo;
        unsigned int *ph, *pl;
        if (zz < 3)      { ph = Wqkvh + zz * 131072; pl = Wqkvl + zz * 131072; }
        else if (zz == 3){ ph = Wph; pl = Wpl; }
        else             { ph = Woh; pl = Wol; }
        split_pack(W[(2 * r) * 512 + n], W[(2 * r + 1) * 512 + n], ph[i], pl[i]);
    } else if (zz == 5) {
        ll i = (ll)bx * 256 + tid;
        float2 v = *(const float2*)(x + 2 * i);
        split_pack(v.x, v.y, xph[i], xpl[i]);
    } else if (zz == 6) {
        if (bx >= 2047) return;
        ll i = (ll)bx * 256 + tid;
        float2 v = *(const float2*)(pos + 2 * i);
        split_pack(v.x, v.y, pph[i], ppl[i]);
    } else {
        if (bx >= 512) return;
        int i = bx * 256 + tid;
        const uchar4* p = (const uchar4*)(mask + (ll)i * 32);
        unsigned int bits = 0;
#pragma unroll
        for (int j = 0; j < 8; j++) {
            uchar4 v = p[j];
            unsigned int q = (v.x ? 1u : 0u) | (v.y ? 2u : 0u) | (v.z ? 4u : 0u) | (v.w ? 8u : 0u);
            bits |= q << (4 * j);
        }
        Mb[i] = bits;
    }
}

// ---------------- bf16x2 pipelined GEMM (ldmatrix fragments) ----------------
// EPACK=0: fp32 C.
// EPACK=1: h==1 packed K (bf16 hi/lo); h==2 V transpose-pack fp16; h==0 fp32 + QR pack (fp16 hi/lo).
// EPACK=2: single-fp16 P pairs.
// EPACK=3 (with TRANSB=1): fp16 A (hi/lo) x single-fp16 B, 2-term, fp16 C.
#define A_STR 20
#define BN_STR 72
#define BT_STR 20
#define G2_SMEM ((4 * 2560 + 4 * 1280) * 4)

template <int TRANSB, int EPACK>
__global__ void __launch_bounds__(256) bf16_gemm(
    const unsigned int* __restrict__ Aph, const unsigned int* __restrict__ Apl,
    int ldap, ll sAb, ll sAh,
    const unsigned int* __restrict__ Bph, const unsigned int* __restrict__ Bpl,
    int ldbp, ll sBb, ll sBh,
    float* __restrict__ C, int ldc, ll sCb, ll sCh,
    int M, int N, int Kp,
    const float* __restrict__ bias0, const float* __restrict__ bias1,
    const float* __restrict__ bias2,
    unsigned int* __restrict__ Ph, unsigned int* __restrict__ Pl,
    const float* __restrict__ pbv,
    unsigned int* __restrict__ QRh, unsigned int* __restrict__ QRl,
    unsigned int* __restrict__ VTh)
{
    constexpr bool F16B = (TRANSB == 1 && EPACK == 3);   // fp16 2-term path (R GEMM)

    extern __shared__ uint32_t su[];
    uint32_t* BH = su + 10240;
    uint32_t* BLo = su + 12800;

    const int z = blockIdx.z, b = z >> 3, h = z & 7;
    const float* bias = (h == 0) ? bias0 : (h == 1) ? bias1 : bias2;
    Aph += (ll)b * sAb + (ll)h * sAh;
    Apl += (ll)b * sAb + (ll)h * sAh;
    Bph += (ll)b * sBb + (ll)h * sBh;
    if (!F16B) Bpl += (ll)b * sBb + (ll)h * sBh;

    const int tid = threadIdx.x;
    const int lane = tid & 31, wid = tid >> 5;
    const int g = lane >> 2, t = lane & 3;
    const int grp = lane >> 3, gi = lane & 7;
    const int wm = wid & 3, wn = wid >> 2;
    const int m0 = blockIdx.y * 128, n0 = blockIdx.x * 64;

    uint32_t sBase = (uint32_t)__cvta_generic_to_shared(su);

    auto stage = [&](int k0p, int stg) {
#pragma unroll
        for (int i = 0; i < 2; i++) {
            int idx = tid + 256 * i;
            int row = idx >> 2, c4 = (idx & 3) << 2;
            bool p = (m0 + row) < M;
            const ll off = (ll)(m0 + row) * ldap + k0p + c4;
            uint32_t d0 = sBase + (uint32_t)(stg * 2560 + row * A_STR + c4) * 4;
            cp_async16(d0, Aph + off, p);
            cp_async16(d0 + 5120 * 4, Apl + off, p);
        }
        if (!TRANSB) {
            int row = tid >> 4, c4 = (tid & 15) << 2;
            const ll off = (ll)(k0p + row) * ldbp + n0 + c4;
            uint32_t d0 = sBase + (uint32_t)(10240 + stg * 1280 + row * BN_STR + c4) * 4;
            cp_async16(d0, Bph + off, true);
            cp_async16(d0 + 2560 * 4, Bpl + off, true);
        } else {
            int row = tid >> 2, c4 = (tid & 3) << 2;
            bool p = (n0 + row) < N;
            const ll off = (ll)(n0 + row) * ldbp + k0p + c4;
            uint32_t d0 = sBase + (uint32_t)(10240 + stg * 1280 + row * BT_STR + c4) * 4;
            cp_async16(d0, Bph + off, p);
            if (!F16B) cp_async16(d0 + 2560 * 4, Bpl + off, p);
        }
    };

    float d[2][4][4];
#pragma unroll
    for (int i = 0; i < 2; i++)
#pragma unroll
        for (int j = 0; j < 4; j++)
#pragma unroll
            for (int c = 0; c < 4; c++) d[i][j][c] = 0.f;

    const int nIter = Kp >> 4;
    stage(0, 0);
    cp_commit();

    for (int it = 0; it < nIter; it++) {
        __syncthreads();
        if (it + 1 < nIter) { stage((it + 1) << 4, (it + 1) & 1); cp_commit(); cp_wait<1>(); }
        else cp_wait<0>();
        __syncthreads();

        const uint32_t aBaseH = sBase +
            (uint32_t)(((it & 1) * 2560 + (wm * 32 + ((grp & 1) << 3) + gi) * A_STR + ((grp >> 1) << 2)) << 2);
        const uint32_t aBaseL = aBaseH + (5120u << 2);
        uint32_t bBaseT = 0;
        if (TRANSB) {
            if (F16B)
                bBaseT = sBase + (uint32_t)((10240 + (it & 1) * 1280 +
                                             (wn * 32 + gi) * BT_STR + ((grp & 1) << 2)) << 2);
            else
                bBaseT = sBase + (uint32_t)((10240 + (grp < 2 ? 0 : 2560) + (it & 1) * 1280 +
                                             (wn * 32 + gi) * BT_STR + ((grp & 1) << 2)) << 2);
        }
        const uint32_t* pBH = BH + (it & 1) * 1280;
        const uint32_t* pBL = BLo + (it & 1) * 1280;

#pragma unroll
        for (int ck = 0; ck < 2; ck++) {
            const int kb = ck * 8;
            uint32_t aH[2][4], aL[2][4];
#pragma unroll
            for (int mt = 0; mt < 2; mt++) {
                uint32_t off = (uint32_t)((mt * 16 * A_STR + kb) << 2);
                ldsm_x4(aH[mt][0], aH[mt][1], aH[mt][2], aH[mt][3], aBaseH + off);
                ldsm_x4(aL[mt][0], aL[mt][1], aL[mt][2], aL[mt][3], aBaseL + off);
            }
#pragma unroll
            for (int nt = 0; nt < 4; nt++) {
                if (F16B) {
                    uint32_t b0, b1;
                    ldsm_x2(b0, b1, bBaseT + (uint32_t)((nt * 8 * BT_STR + kb) << 2));
#pragma unroll
                    for (int mt = 0; mt < 2; mt++) {
                        mma_f16(d[mt][nt], aH[mt], b0, b1);
                        mma_f16(d[mt][nt], aL[mt], b0, b1);
                    }
                } else {
                    uint32_t b0h, b1h, b0l, b1l;
                    if (!TRANSB) {
                        int col = wn * 32 + nt * 8 + g;
                        int i0 = (kb + t) * BN_STR + col, i1 = (kb + t + 4) * BN_STR + col;
                        b0h = pBH[i0]; b1h = pBH[i1];
                        b0l = pBL[i0]; b1l = pBL[i1];
                    } else {
                        ldsm_x4(b0h, b1h, b0l, b1l, bBaseT + (uint32_t)((nt * 8 * BT_STR + kb) << 2));
                    }
#pragma unroll
                    for (int mt = 0; mt < 2; mt++) {
                        mma_bf16(d[mt][nt], aH[mt], b0h, b1h);
                        mma_bf16(d[mt][nt], aL[mt], b0h, b1h);
                        mma_bf16(d[mt][nt], aH[mt], b0l, b1l);
                    }
                }
            }
        }
    }

    // ---- epilogue ----
    const bool packK = (EPACK == 1 && h == 1);
    if (EPACK == 2 || packK) {
#pragma unroll
        for (int mt = 0; mt < 2; mt++) {
#pragma unroll
            for (int nt = 0; nt < 4; nt++) {
                int col = n0 + wn * 32 + nt * 8 + 2 * t;
                float b0 = bias ? bias[col] : 0.f;
                float b1 = bias ? bias[col + 1] : 0.f;
#pragma unroll
                for (int rr = 0; rr < 2; rr++) {
                    int row = m0 + wm * 32 + mt * 16 + g + 8 * rr;
                    if (row >= M) continue;
                    float v0 = d[mt][nt][2 * rr + 0] + b0;
                    float v1 = d[mt][nt][2 * rr + 1] + b1;
                    if (EPACK == 2) {
                        Ph[(ll)row * 256 + (col >> 1)] = pack_f16(v0, v1);   // single fp16
                    } else {
                        int zk = ((row >> 10) << 3) + (col >> 6);
                        ll idx = ((ll)zk * 1024 + (row & 1023)) * 32 + ((col & 63) >> 1);
                        split_pack(v0, v1, Ph[idx], Pl[idx]);
                    }
                }
            }
        }
        return;
    }

    if (EPACK == 1 && h == 2) {
        float* sv = (float*)su;   // [128][68]
        __syncthreads();
#pragma unroll
        for (int mt = 0; mt < 2; mt++) {
#pragma unroll
            for (int nt = 0; nt < 4; nt++) {
                int cl = wn * 32 + nt * 8 + 2 * t;
                float b0 = bias[n0 + cl], b1 = bias[n0 + cl + 1];
#pragma unroll
                for (int rr = 0; rr < 2; rr++) {
                    int rl = wm * 32 + mt * 16 + g + 8 * rr;
                    sv[rl * 68 + cl]     = d[mt][nt][2 * rr + 0] + b0;
                    sv[rl * 68 + cl + 1] = d[mt][nt][2 * rr + 1] + b1;
                }
            }
        }
        __syncthreads();
        const int bb = m0 >> 10, s0 = m0 & 1023, head = n0 >> 6;
        const int zv = bb * 8 + head;
        const int dd = tid & 63, sg = tid >> 6;
        ll base = ((ll)zv * 64 + dd) * 512 + ((s0 + sg * 32) >> 1);
#pragma unroll
        for (int j = 0; j < 16; j++)
            VTh[base + j] = pack_f16(sv[(sg * 32 + 2 * j) * 68 + dd],
                                     sv[(sg * 32 + 2 * j + 1) * 68 + dd]);
        return;
    }

    if (EPACK == 3) {
        __half* Cz = (__half*)C + (ll)b * sCb + (ll)h * sCh;
#pragma unroll
        for (int mt = 0; mt < 2; mt++) {
#pragma unroll
            for (int nt = 0; nt < 4; nt++) {
                int col = n0 + wn * 32 + nt * 8 + 2 * t;
#pragma unroll
                for (int rr = 0; rr < 2; rr++) {
                    int row = m0 + wm * 32 + mt * 16 + g + 8 * rr;
                    if (row >= M) continue;
                    float v0 = d[mt][nt][2 * rr + 0];
                    float v1 = d[mt][nt][2 * rr + 1];
                    if (col + 1 < N)
                        *(__half2*)(Cz + (ll)row * ldc + col) = __floats2half2_rn(v0, v1);
                    else if (col < N)
                        Cz[(ll)row * ldc + col] = __float2half(v0);
                }
            }
        }
        return;
    }

    float* Cz = C + (ll)b * sCb + (ll)h * sCh;
#pragma unroll
    for (int mt = 0; mt < 2; mt++) {
#pragma unroll
        for (int nt = 0; nt < 4; nt++) {
            int col = n0 + wn * 32 + nt * 8 + 2 * t;
            float b0 = (bias && col < N) ? bias[col] : 0.f;
            float b1 = (bias && col + 1 < N) ? bias[col + 1] : 0.f;
#pragma unroll
            for (int rr = 0; rr < 2; rr++) {
                int row = m0 + wm * 32 + mt * 16 + g + 8 * rr;
                if (row >= M) continue;
                float v0 = d[mt][nt][2 * rr + 0] + b0;
                float v1 = d[mt][nt][2 * rr + 1] + b1;
                if (col < N)     Cz[(ll)row * ldc + col]     = v0;
                if (col + 1 < N) Cz[(ll)row * ldc + col + 1] = v1;
                if (EPACK == 1 && h == 0) {
                    int tloc = row & 1023;
                    if (tloc >= 512) {
                        int zq = ((row >> 10) << 3) + (col >> 6);
                        ll qi = ((ll)zq * 512 + (tloc - 512)) * 32 + ((col & 63) >> 1);
                        split_pack_f16(v0 + pbv[col], v1 + pbv[col + 1], QRh[qi], QRl[qi]);
                    }
                }
            }
        }
    }
}

// ---------------- fused flash attention: bf16x2 QK (3-term), fp16 PV (2-term), fp16 R ----------------
#define PSTR 36
#define FL_SMEM (6 * 2304 * 4)

__global__ void __launch_bounds__(128, 3) flash_attn(
    const float* __restrict__ Q,
    const unsigned int* __restrict__ Kph, const unsigned int* __restrict__ Kpl,
    const unsigned int* __restrict__ VTh,
    const float* __restrict__ pbu, const __half* __restrict__ Rr,
    const unsigned int* __restrict__ mbits,
    unsigned int* __restrict__ Oph, unsigned int* __restrict__ Opl)
{
    extern __shared__ uint32_t smu[];
    uint32_t* VH = smu + 4 * 2304;

    const int z = blockIdx.y, b = z >> 3, h = z & 7;
    const int t0 = blockIdx.x * 64;
    const int tid = threadIdx.x, lane = tid & 31, w = tid >> 5;
    const int g = lane >> 2, t = lane & 3;
    const int grp = lane >> 3, gi = lane & 7;

    const float* Qb = Q + ((ll)(b * TT + t0)) * DM + h * DK;
    const ll rb = (ll)z * 512 * RSTR;

    uint32_t qh[4][4], ql[4][4];
    {
        const int r0 = w * 16 + g, r1 = r0 + 8;
#pragma unroll
        for (int ks = 0; ks < 4; ks++) {
#pragma unroll
            for (int half = 0; half < 2; half++) {
                int c = 16 * ks + 8 * half + 2 * t;
                float u0 = pbu[h * DK + c], u1 = pbu[h * DK + c + 1];
                float x0 = Qb[(ll)r0 * DM + c] + u0;
                float x1 = Qb[(ll)r0 * DM + c + 1] + u1;
                float y0 = Qb[(ll)r1 * DM + c] + u0;
                float y1 = Qb[(ll)r1 * DM + c + 1] + u1;
                split_pack(x0, x1, qh[ks][2 * half + 0], ql[ks][2 * half + 0]);
                split_pack(y0, y1, qh[ks][2 * half + 1], ql[ks][2 * half + 1]);
            }
        }
    }

    float o[8][4];
#pragma unroll
    for (int i = 0; i < 8; i++)
#pragma unroll
        for (int j = 0; j < 4; j++) o[i][j] = 0.f;
    float mx0 = -1e30f, mx1 = -1e30f, l0 = 0.f, l1 = 0.f;

    uint32_t sBase = (uint32_t)__cvta_generic_to_shared(smu);

    auto loadKV = [&](int st, int buf) {
        const unsigned int* kh = Kph + ((ll)z * 1024 + st * 64) * 32;
        const unsigned int* kl = Kpl + ((ll)z * 1024 + st * 64) * 32;
        const unsigned int* vh = VTh + (ll)z * 64 * 512 + st * 32;
        uint32_t o0 = sBase + (uint32_t)(buf * 2304) * 4;
#pragma unroll
        for (int i = 0; i < 4; i++) {
            int idx = tid + 128 * i;
            int row = idx >> 3, c4 = (idx & 7) << 2;
            uint32_t soff = (uint32_t)(row * PSTR + c4) * 4;
            cp_async16(o0 + soff,                kh + (ll)row * 32 + c4, true);
            cp_async16(o0 + 2 * 2304 * 4 + soff, kl + (ll)row * 32 + c4, true);
            cp_async16(o0 + 4 * 2304 * 4 + soff, vh + (ll)row * 512 + c4, true);
        }
    };

    loadKV(0, 0);
    cp_commit();

    const int tg0 = t0 + w * 16 + g, tg1 = tg0 + 8;
    const __half2* R0 = (const __half2*)(Rr + rb + (ll)(tg0 >> 1) * RSTR);
    const __half2* R1 = (const __half2*)(Rr + rb + (ll)(tg1 >> 1) * RSTR);
    const int p0 = (tg0 & 1) << 10, p1 = (tg1 & 1) << 10;
    const uint2* mrow0 = (const uint2*)(mbits + ((ll)b * TT + tg0) * 32);
    const uint2* mrow1 = (const uint2*)(mbits + ((ll)b * TT + tg1) * 32);

    for (int st = 0; st < 16; st++) {
        const int buf = st & 1;
        cp_wait<0>();
        __syncthreads();
        if (st + 1 < 16) { loadKV(st + 1, 1 - buf); cp_commit(); }

        const uint32_t kAddr = sBase +
            (uint32_t)((((grp < 2 ? buf : 2 + buf) * 2304) + gi * PSTR + ((grp & 1) << 2)) << 2);
        const uint32_t* pVH = VH + buf * 2304;

        float sc[8][4];
#pragma unroll
        for (int i = 0; i < 8; i++)
#pragma unroll
            for (int j = 0; j < 4; j++) sc[i][j] = 0.f;
#pragma unroll
        for (int nt = 0; nt < 8; nt++) {
#pragma unroll
            for (int ks = 0; ks < 4; ks++) {
                uint32_t b0h, b1h, b0l, b1l;
                ldsm_x4(b0h, b1h, b0l, b1l, kAddr + (uint32_t)((nt * 8 * PSTR + 8 * ks) << 2));
                mma_bf16(sc[nt], qh[ks], b0h, b1h);
                mma_bf16(sc[nt], ql[ks], b0h, b1h);
                mma_bf16(sc[nt], qh[ks], b0l, b1l);
            }
        }

        const int s0 = st * 64;
#pragma unroll
        for (int nt = 0; nt < 8; nt++) {
            int s_ = s0 + nt * 8 + 2 * t;
            int la = s_ + p0, lb = s_ + p1;
            float2 va = __half22float2(R0[la >> 1]);
            float2 vb = __half22float2(R1[lb >> 1]);
            float pa1 = (la + 1 == LL) ? 0.f : va.y;
            float pb1 = (lb + 1 == LL) ? 0.f : vb.y;
            sc[nt][0] = (sc[nt][0] + va.x) * 0.125f;
            sc[nt][1] = (sc[nt][1] + pa1) * 0.125f;
            sc[nt][2] = (sc[nt][2] + vb.x) * 0.125f;
            sc[nt][3] = (sc[nt][3] + pb1) * 0.125f;
        }
        {
            uint2 w0 = mrow0[st], w1 = mrow1[st];
            u64 m0 = (u64)w0.x | ((u64)w0.y << 32);
            u64 m1 = (u64)w1.x | ((u64)w1.y << 32);
            if (m0 | m1) {
#pragma unroll
                for (int nt = 0; nt < 8; nt++) {
                    int p = nt * 8 + 2 * t;
                    if ((m0 >> p) & 1)       sc[nt][0] = -1e9f;
                    if ((m0 >> (p + 1)) & 1) sc[nt][1] = -1e9f;
                    if ((m1 >> p) & 1)       sc[nt][2] = -1e9f;
                    if ((m1 >> (p + 1)) & 1) sc[nt][3] = -1e9f;
                }
            }
        }

        float rmx0 = -1e30f, rmx1 = -1e30f;
#pragma unroll
        for (int nt = 0; nt < 8; nt++) {
            rmx0 = fmaxf(rmx0, fmaxf(sc[nt][0], sc[nt][1]));
            rmx1 = fmaxf(rmx1, fmaxf(sc[nt][2], sc[nt][3]));
        }
        rmx0 = fmaxf(rmx0, __shfl_xor_sync(0xffffffffu, rmx0, 1));
        rmx0 = fmaxf(rmx0, __shfl_xor_sync(0xffffffffu, rmx0, 2));
        rmx1 = fmaxf(rmx1, __shfl_xor_sync(0xffffffffu, rmx1, 1));
        rmx1 = fmaxf(rmx1, __shfl_xor_sync(0xffffffffu, rmx1, 2));

        float mn0 = fmaxf(mx0, rmx0), mn1 = fmaxf(mx1, rmx1);
        float al0 = __expf(mx0 - mn0), al1 = __expf(mx1 - mn1);
        float rs0 = 0.f, rs1 = 0.f;
#pragma unroll
        for (int nt = 0; nt < 8; nt++) {
            sc[nt][0] = __expf(sc[nt][0] - mn0);
            sc[nt][1] = __expf(sc[nt][1] - mn0);
            sc[nt][2] = __expf(sc[nt][2] - mn1);
            sc[nt][3] = __expf(sc[nt][3] - mn1);
            rs0 += sc[nt][0] + sc[nt][1];
            rs1 += sc[nt][2] + sc[nt][3];
        }
        rs0 += __shfl_xor_sync(0xffffffffu, rs0, 1);
        rs0 += __shfl_xor_sync(0xffffffffu, rs0, 2);
        rs1 += __shfl_xor_sync(0xffffffffu, rs1, 1);
        rs1 += __shfl_xor_sync(0xffffffffu, rs1, 2);
        l0 = l0 * al0 + rs0;
        l1 = l1 * al1 + rs1;
        mx0 = mn0; mx1 = mn1;
#pragma unroll
        for (int dt = 0; dt < 8; dt++) {
            o[dt][0] *= al0; o[dt][1] *= al0;
            o[dt][2] *= al1; o[dt][3] *= al1;
        }

        // ---- O += P @ V : fp16 2-term ----
#pragma unroll
        for (int j = 0; j < 4; j++) {
            uint32_t aPh[4], aPl[4];
            split_pack_f16(sc[2 * j][0],     sc[2 * j][1],     aPh[0], aPl[0]);
            split_pack_f16(sc[2 * j][2],     sc[2 * j][3],     aPh[1], aPl[1]);
            split_pack_f16(sc[2 * j + 1][0], sc[2 * j + 1][1], aPh[2], aPl[2]);
            split_pack_f16(sc[2 * j + 1][2], sc[2 * j + 1][3], aPh[3], aPl[3]);
#pragma unroll
            for (int dt = 0; dt < 8; dt++) {
                const int vrow = (dt * 8 + g) * PSTR;
                uint32_t b0h = pVH[vrow + 8 * j + t];
                uint32_t b1h = pVH[vrow + 8 * j + 4 + t];
                mma_f16(o[dt], aPh, b0h, b1h);
                mma_f16(o[dt], aPl, b0h, b1h);
            }
        }
    }

    float inv0 = 1.f / l0, inv1 = 1.f / l1;
    ll base0 = ((ll)(b * TT + tg0)) * 256 + h * 32;
    ll base1 = ((ll)(b * TT + tg1)) * 256 + h * 32;
#pragma unroll
    for (int dt = 0; dt < 8; dt++) {
        int pj = dt * 4 + t;
        split_pack(o[dt][0] * inv0, o[dt][1] * inv0, Oph[base0 + pj], Opl[base0 + pj]);
        split_pack(o[dt][2] * inv1, o[dt][3] * inv1, Oph[base1 + pj], Opl[base1 + pj]);
    }
}

// ---------------- launch ----------------
extern "C" void kernel_launch(void* const* d_in, const int* in_sizes, int n_in,
                              void* d_out, int out_size)
{
    const float* x   = (const float*)d_in[0];
    const float* pos = (const float*)d_in[1];
    const unsigned char* mask = (const unsigned char*)d_in[2];
    const float* Wq = (const float*)d_in[3];  const float* bq = (const float*)d_in[4];
    const float* Wk = (const float*)d_in[5];  const float* bk = (const float*)d_in[6];
    const float* Wv = (const float*)d_in[7];  const float* bv = (const float*)d_in[8];
    const float* Wp = (const float*)d_in[9];  const float* bp = (const float*)d_in[10];
    const float* Wo = (const float*)d_in[11]; const float* bo = (const float*)d_in[12];
    const float* pbu = (const float*)d_in[13];
    const float* pbv = (const float*)d_in[14];
    float* out = (float*)d_out;

    float *QKV;
    __half* Rh;
    unsigned int *Mb, *Kph, *Kpl, *VTh;
    unsigned int *xph, *xpl, *pph, *ppl, *Pph, *QRh, *QRl, *Oph, *Opl;
    unsigned int *Wqkvh, *Wqkvl, *Wph_, *Wpl_, *Woh, *Wol;
    cudaGetSymbolAddress((void**)&QKV, g_QKV);
    cudaGetSymbolAddress((void**)&Rh, g_Rh);
    cudaGetSymbolAddress((void**)&Mb, g_Mb);
    cudaGetSymbolAddress((void**)&Kph, g_Kph);
    cudaGetSymbolAddress((void**)&Kpl, g_Kpl);
    cudaGetSymbolAddress((void**)&VTh, g_VTh);
    cudaGetSymbolAddress((void**)&xph, g_xph);
    cudaGetSymbolAddress((void**)&xpl, g_xpl);
    cudaGetSymbolAddress((void**)&pph, g_pph);
    cudaGetSymbolAddress((void**)&ppl, g_ppl);
    cudaGetSymbolAddress((void**)&Pph, g_Pph);
    cudaGetSymbolAddress((void**)&QRh, g_QRh);
    cudaGetSymbolAddress((void**)&QRl, g_QRl);
    cudaGetSymbolAddress((void**)&Oph, g_Oph);
    cudaGetSymbolAddress((void**)&Opl, g_Opl);
    cudaGetSymbolAddress((void**)&Wqkvh, g_Wqkvh);
    cudaGetSymbolAddress((void**)&Wqkvl, g_Wqkvl);
    cudaGetSymbolAddress((void**)&Wph_, g_Wph);
    cudaGetSymbolAddress((void**)&Wpl_, g_Wpl);
    cudaGetSymbolAddress((void**)&Woh, g_Woh);
    cudaGetSymbolAddress((void**)&Wol, g_Wol);

    cudaFuncSetAttribute((const void*)bf16_gemm<0, 0>, cudaFuncAttributeMaxDynamicSharedMemorySize, G2_SMEM);
    cudaFuncSetAttribute((const void*)bf16_gemm<0, 1>, cudaFuncAttributeMaxDynamicSharedMemorySize, G2_SMEM);
    cudaFuncSetAttribute((const void*)bf16_gemm<0, 2>, cudaFuncAttributeMaxDynamicSharedMemorySize, G2_SMEM);
    cudaFuncSetAttribute((const void*)bf16_gemm<1, 3>, cudaFuncAttributeMaxDynamicSharedMemorySize, G2_SMEM);
    cudaFuncSetAttribute((const void*)flash_attn, cudaFuncAttributeMaxDynamicSharedMemorySize, FL_SMEM);

    dim3 blk(256);

    // 1) all independent packs
    megapack1<<<dim3(4096, 1, 8), blk>>>(
        x, pos, mask, Wq, Wk, Wv, Wp, Wo,
        Wqkvh, Wqkvl, Wph_, Wpl_, Woh, Wol, xph, xpl, pph, ppl, Mb);

    // 2) fused Q/K/V projection:
    //    h==0: fp32 Q + fp16 QR pack (rows>=512); h==1: packed K; h==2: transposed fp16 V
    bf16_gemm<0, 1><<<dim3(8, 32, 3), blk, G2_SMEM>>>(
        xph, xpl, 256, 0, 0,
        Wqkvh, Wqkvl, 512, 0, 131072,
        QKV, DM, 0, 2097152,
        NB * TT, DM, 256, bq, bk, bv, Kph, Kpl, pbv, QRh, QRl, VTh);

    // 3) P projection -> single-fp16 packed Pph
    bf16_gemm<0, 2><<<dim3(8, 16, 1), blk, G2_SMEM>>>(
        pph, ppl, 256, 0, 0, Wph_, Wpl_, 512, 0, 0,
        nullptr, DM, 0, 0, LL, DM, 256, bp, bp, bp, Pph, nullptr, nullptr, nullptr, nullptr, nullptr);

    // 4) R = (Q[512:]+pbv) @ P^T per (b,h): fp16 2-term, fp16 output
    bf16_gemm<1, 3><<<dim3(32, 4, 32), blk, G2_SMEM>>>(
        QRh, QRl, 32, 8LL * 512 * 32, 512 * 32,
        Pph, nullptr, 256, 0, 32,
        (float*)Rh, RSTR, 8LL * 512 * RSTR, (ll)512 * RSTR,
        512, LL, 32, nullptr, nullptr, nullptr, nullptr, nullptr, nullptr, nullptr, nullptr, nullptr);

    // 5) flash attention (fp16 R)
    flash_attn<<<dim3(16, 32), dim3(128), FL_SMEM>>>(
        QKV, Kph, Kpl, VTh, pbu, Rh, Mb, Oph, Opl);

    // 6) out = O @ Wo + bo
    bf16_gemm<0, 0><<<dim3(8, 32, 1), blk, G2_SMEM>>>(
        Oph, Opl, 256, 0, 0, Woh, Wol, 512, 0, 0,
        out, DM, 0, 0, NB * TT, DM, 256, bo, bo, bo, nullptr, nullptr, nullptr, nullptr, nullptr, nullptr);
}

// round 16
// speedup vs baseline: 1.5319x; 1.5319x over previous
#include <cuda_runtime.h>
#include <cuda_bf16.h>
#include <cuda_fp16.h>
#include <cstdint>

#define TT 1024
#define DM 512
#define NB 4
#define NH 8
#define DK 64
#define LL 2047   // 2*T - 1
#define RSTR 2048
typedef long long ll;
typedef unsigned long long u64;

// ---------------- scratch ----------------
__device__ float g_QKV[3LL * NB * TT * DM];     // Q | (K,V unused)
__device__ __half g_Rh[32LL * 512 * RSTR];      // R in fp16
__device__ unsigned int g_Mb[NB * TT * 32];
__device__ unsigned int g_Kph[32LL * 1024 * 32];
__device__ unsigned int g_Kpl[32LL * 1024 * 32];
__device__ unsigned int g_VTh[32LL * 64 * 512];   // fp16x2 pairs along s
__device__ unsigned int g_xph[NB * TT * 256],  g_xpl[NB * TT * 256];
__device__ unsigned int g_pph[2047 * 256],     g_ppl[2047 * 256];
__device__ unsigned int g_Wqkvh[3 * 256 * 512], g_Wqkvl[3 * 256 * 512];
__device__ unsigned int g_Wph[256 * 512], g_Wpl[256 * 512];
__device__ unsigned int g_Woh[256 * 512], g_Wol[256 * 512];
__device__ unsigned int g_Pph[2047 * 256], g_Ppl[2047 * 256];
__device__ unsigned int g_QRh[32LL * 512 * 32], g_QRl[32LL * 512 * 32];
__device__ unsigned int g_Oph[NB * TT * 256], g_Opl[NB * TT * 256];

// ---------------- helpers ----------------
__device__ __forceinline__ float bf16_hi(float x) {
    return __bfloat162float(__float2bfloat16(x));
}
__device__ __forceinline__ uint32_t pack_bf16(float lo_elem, float hi_elem) {
    uint32_t r;
    asm("cvt.rn.bf16x2.f32 %0, %1, %2;" : "=r"(r) : "f"(hi_elem), "f"(lo_elem));
    return r;
}
__device__ __forceinline__ void split_pack(float a, float b, uint32_t& ph, uint32_t& pl) {
    float ha = bf16_hi(a), hb = bf16_hi(b);
    ph = pack_bf16(a, b);
    pl = pack_bf16(a - ha, b - hb);
}
__device__ __forceinline__ float f16_hi(float x) {
    return __half2float(__float2half_rn(x));
}
__device__ __forceinline__ uint32_t pack_f16(float lo_elem, float hi_elem) {
    uint32_t r;
    asm("cvt.rn.f16x2.f32 %0, %1, %2;" : "=r"(r) : "f"(hi_elem), "f"(lo_elem));
    return r;
}
__device__ __forceinline__ void split_pack_f16(float a, float b, uint32_t& ph, uint32_t& pl) {
    float ha = f16_hi(a), hb = f16_hi(b);
    ph = pack_f16(a, b);
    pl = pack_f16(a - ha, b - hb);
}
__device__ __forceinline__ void mma_bf16(float* d, const uint32_t* a, uint32_t b0, uint32_t b1) {
    asm volatile(
        "mma.sync.aligned.m16n8k16.row.col.f32.bf16.bf16.f32 "
        "{%0,%1,%2,%3}, {%4,%5,%6,%7}, {%8,%9}, {%0,%1,%2,%3};\n"
        : "+f"(d[0]), "+f"(d[1]), "+f"(d[2]), "+f"(d[3])
        : "r"(a[0]), "r"(a[1]), "r"(a[2]), "r"(a[3]), "r"(b0), "r"(b1));
}
__device__ __forceinline__ void mma_f16(float* d, const uint32_t* a, uint32_t b0, uint32_t b1) {
    asm volatile(
        "mma.sync.aligned.m16n8k16.row.col.f32.f16.f16.f32 "
        "{%0,%1,%2,%3}, {%4,%5,%6,%7}, {%8,%9}, {%0,%1,%2,%3};\n"
        : "+f"(d[0]), "+f"(d[1]), "+f"(d[2]), "+f"(d[3])
        : "r"(a[0]), "r"(a[1]), "r"(a[2]), "r"(a[3]), "r"(b0), "r"(b1));
}
__device__ __forceinline__ void ldsm_x4(uint32_t& r0, uint32_t& r1, uint32_t& r2, uint32_t& r3,
                                        uint32_t addr) {
    asm volatile("ldmatrix.sync.aligned.m8n8.x4.shared.b16 {%0,%1,%2,%3}, [%4];\n"
                 : "=r"(r0), "=r"(r1), "=r"(r2), "=r"(r3) : "r"(addr));
}
__device__ __forceinline__ void cp_async16(uint32_t dst, const void* src, bool p) {
    asm volatile("cp.async.cg.shared.global [%0], [%1], 16, %2;\n"
                 :: "r"(dst), "l"(src), "r"(p ? 16 : 0));
}
__device__ __forceinline__ void cp_commit() { asm volatile("cp.async.commit_group;\n"); }
template <int N>
__device__ __forceinline__ void cp_wait() { asm volatile("cp.async.wait_group %0;\n" :: "n"(N)); }

// ---------------- mega-pack 1: all input-only packs, grid (4096,1,8) ----------------
__global__ void __launch_bounds__(256) megapack1(
    const float* __restrict__ x, const float* __restrict__ pos,
    const unsigned char* __restrict__ mask,
    const float* __restrict__ Wq, const float* __restrict__ Wk,
    const float* __restrict__ Wv, const float* __restrict__ Wp,
    const float* __restrict__ Wo,
    unsigned int* __restrict__ Wqkvh, unsigned int* __restrict__ Wqkvl,
    unsigned int* __restrict__ Wph, unsigned int* __restrict__ Wpl,
    unsigned int* __restrict__ Woh, unsigned int* __restrict__ Wol,
    unsigned int* __restrict__ xph, unsigned int* __restrict__ xpl,
    unsigned int* __restrict__ pph, unsigned int* __restrict__ ppl,
    unsigned int* __restrict__ Mb)
{
    const int zz = blockIdx.z, bx = blockIdx.x, tid = threadIdx.x;
    if (zz < 5) {
        if (bx >= 512) return;
        int i = bx * 256 + tid;
        int r = i >> 9, n = i & 511;
        const float* W = zz == 0 ? Wq : zz == 1 ? Wk : zz == 2 ? Wv : zz == 3 ? Wp : Wo;
        unsigned int *ph, *pl;
        if (zz < 3)      { ph = Wqkvh + zz * 131072; pl = Wqkvl + zz * 131072; }
        else if (zz == 3){ ph = Wph; pl = Wpl; }
        else             { ph = Woh; pl = Wol; }
        split_pack(W[(2 * r) * 512 + n], W[(2 * r + 1) * 512 + n], ph[i], pl[i]);
    } else if (zz == 5) {
        ll i = (ll)bx * 256 + tid;
        float2 v = *(const float2*)(x + 2 * i);
        split_pack(v.x, v.y, xph[i], xpl[i]);
    } else if (zz == 6) {
        if (bx >= 2047) return;
        ll i = (ll)bx * 256 + tid;
        float2 v = *(const float2*)(pos + 2 * i);
        split_pack(v.x, v.y, pph[i], ppl[i]);
    } else {
        if (bx >= 512) return;
        int i = bx * 256 + tid;
        const uchar4* p = (const uchar4*)(mask + (ll)i * 32);
        unsigned int bits = 0;
#pragma unroll
        for (int j = 0; j < 8; j++) {
            uchar4 v = p[j];
            unsigned int q = (v.x ? 1u : 0u) | (v.y ? 2u : 0u) | (v.z ? 4u : 0u) | (v.w ? 8u : 0u);
            bits |= q << (4 * j);
        }
        Mb[i] = bits;
    }
}

// ---------------- bf16x2 pipelined GEMM (ldmatrix fragments) ----------------
// EPACK=0: fp32 C.
// EPACK=1: h==1 packed K; h==2 V transpose-pack (fp16, via smem); h==0 fp32 + QR pack.
// EPACK=2: packed P pairs. EPACK=3: fp16 C.
#define A_STR 20
#define BN_STR 72
#define BT_STR 20
#define G2_SMEM ((4 * 2560 + 4 * 1280) * 4)

template <int TRANSB, int EPACK>
__global__ void __launch_bounds__(256) bf16_gemm(
    const unsigned int* __restrict__ Aph, const unsigned int* __restrict__ Apl,
    int ldap, ll sAb, ll sAh,
    const unsigned int* __restrict__ Bph, const unsigned int* __restrict__ Bpl,
    int ldbp, ll sBb, ll sBh,
    float* __restrict__ C, int ldc, ll sCb, ll sCh,
    int M, int N, int Kp,
    const float* __restrict__ bias0, const float* __restrict__ bias1,
    const float* __restrict__ bias2,
    unsigned int* __restrict__ Ph, unsigned int* __restrict__ Pl,
    const float* __restrict__ pbv,
    unsigned int* __restrict__ QRh, unsigned int* __restrict__ QRl,
    unsigned int* __restrict__ VTh)
{
    extern __shared__ uint32_t su[];
    uint32_t* BH = su + 10240;
    uint32_t* BLo = su + 12800;

    const int z = blockIdx.z, b = z >> 3, h = z & 7;
    const float* bias = (h == 0) ? bias0 : (h == 1) ? bias1 : bias2;
    Aph += (ll)b * sAb + (ll)h * sAh;
    Apl += (ll)b * sAb + (ll)h * sAh;
    Bph += (ll)b * sBb + (ll)h * sBh;
    Bpl += (ll)b * sBb + (ll)h * sBh;

    const int tid = threadIdx.x;
    const int lane = tid & 31, wid = tid >> 5;
    const int g = lane >> 2, t = lane & 3;
    const int grp = lane >> 3, gi = lane & 7;
    const int wm = wid & 3, wn = wid >> 2;
    const int m0 = blockIdx.y * 128, n0 = blockIdx.x * 64;

    uint32_t sBase = (uint32_t)__cvta_generic_to_shared(su);

    auto stage = [&](int k0p, int stg) {
#pragma unroll
        for (int i = 0; i < 2; i++) {
            int idx = tid + 256 * i;
            int row = idx >> 2, c4 = (idx & 3) << 2;
            bool p = (m0 + row) < M;
            const ll off = (ll)(m0 + row) * ldap + k0p + c4;
            uint32_t d0 = sBase + (uint32_t)(stg * 2560 + row * A_STR + c4) * 4;
            cp_async16(d0, Aph + off, p);
            cp_async16(d0 + 5120 * 4, Apl + off, p);
        }
        if (!TRANSB) {
            int row = tid >> 4, c4 = (tid & 15) << 2;
            const ll off = (ll)(k0p + row) * ldbp + n0 + c4;
            uint32_t d0 = sBase + (uint32_t)(10240 + stg * 1280 + row * BN_STR + c4) * 4;
            cp_async16(d0, Bph + off, true);
            cp_async16(d0 + 2560 * 4, Bpl + off, true);
        } else {
            int row = tid >> 2, c4 = (tid & 3) << 2;
            bool p = (n0 + row) < N;
            const ll off = (ll)(n0 + row) * ldbp + k0p + c4;
            uint32_t d0 = sBase + (uint32_t)(10240 + stg * 1280 + row * BT_STR + c4) * 4;
            cp_async16(d0, Bph + off, p);
            cp_async16(d0 + 2560 * 4, Bpl + off, p);
        }
    };

    float d[2][4][4];
#pragma unroll
    for (int i = 0; i < 2; i++)
#pragma unroll
        for (int j = 0; j < 4; j++)
#pragma unroll
            for (int c = 0; c < 4; c++) d[i][j][c] = 0.f;

    const int nIter = Kp >> 4;
    stage(0, 0);
    cp_commit();

    for (int it = 0; it < nIter; it++) {
        __syncthreads();
        if (it + 1 < nIter) { stage((it + 1) << 4, (it + 1) & 1); cp_commit(); cp_wait<1>(); }
        else cp_wait<0>();
        __syncthreads();

        const uint32_t aBaseH = sBase +
            (uint32_t)(((it & 1) * 2560 + (wm * 32 + ((grp & 1) << 3) + gi) * A_STR + ((grp >> 1) << 2)) << 2);
        const uint32_t aBaseL = aBaseH + (5120u << 2);
        uint32_t bBaseT = 0;
        if (TRANSB)
            bBaseT = sBase + (uint32_t)((10240 + (grp < 2 ? 0 : 2560) + (it & 1) * 1280 +
                                         (wn * 32 + gi) * BT_STR + ((grp & 1) << 2)) << 2);
        const uint32_t* pBH = BH + (it & 1) * 1280;
        const uint32_t* pBL = BLo + (it & 1) * 1280;

#pragma unroll
        for (int ck = 0; ck < 2; ck++) {
            const int kb = ck * 8;
            uint32_t aH[2][4], aL[2][4];
#pragma unroll
            for (int mt = 0; mt < 2; mt++) {
                uint32_t off = (uint32_t)((mt * 16 * A_STR + kb) << 2);
                ldsm_x4(aH[mt][0], aH[mt][1], aH[mt][2], aH[mt][3], aBaseH + off);
                ldsm_x4(aL[mt][0], aL[mt][1], aL[mt][2], aL[mt][3], aBaseL + off);
            }
#pragma unroll
            for (int nt = 0; nt < 4; nt++) {
                uint32_t b0h, b1h, b0l, b1l;
                if (!TRANSB) {
                    int col = wn * 32 + nt * 8 + g;
                    int i0 = (kb + t) * BN_STR + col, i1 = (kb + t + 4) * BN_STR + col;
                    b0h = pBH[i0]; b1h = pBH[i1];
                    b0l = pBL[i0]; b1l = pBL[i1];
                } else {
                    ldsm_x4(b0h, b1h, b0l, b1l, bBaseT + (uint32_t)((nt * 8 * BT_STR + kb) << 2));
                }
#pragma unroll
                for (int mt = 0; mt < 2; mt++) {
                    mma_bf16(d[mt][nt], aH[mt], b0h, b1h);
                    mma_bf16(d[mt][nt], aL[mt], b0h, b1h);
                    mma_bf16(d[mt][nt], aH[mt], b0l, b1l);
                }
            }
        }
    }

    // ---- epilogue ----
    const bool packK = (EPACK == 1 && h == 1);
    if (EPACK == 2 || packK) {
#pragma unroll
        for (int mt = 0; mt < 2; mt++) {
#pragma unroll
            for (int nt = 0; nt < 4; nt++) {
                int col = n0 + wn * 32 + nt * 8 + 2 * t;
                float b0 = bias ? bias[col] : 0.f;
                float b1 = bias ? bias[col + 1] : 0.f;
#pragma unroll
                for (int rr = 0; rr < 2; rr++) {
                    int row = m0 + wm * 32 + mt * 16 + g + 8 * rr;
                    if (row >= M) continue;
                    float v0 = d[mt][nt][2 * rr + 0] + b0;
                    float v1 = d[mt][nt][2 * rr + 1] + b1;
                    ll idx;
                    if (EPACK == 2) {
                        idx = (ll)row * 256 + (col >> 1);
                    } else {
                        int zk = ((row >> 10) << 3) + (col >> 6);
                        idx = ((ll)zk * 1024 + (row & 1023)) * 32 + ((col & 63) >> 1);
                    }
                    split_pack(v0, v1, Ph[idx], Pl[idx]);
                }
            }
        }
        return;
    }

    if (EPACK == 1 && h == 2) {
        // V slab: transpose-pack to VTh via smem staging (fp16 pairs along s)
        float* sv = (float*)su;   // [128][68]
        __syncthreads();
#pragma unroll
        for (int mt = 0; mt < 2; mt++) {
#pragma unroll
            for (int nt = 0; nt < 4; nt++) {
                int cl = wn * 32 + nt * 8 + 2 * t;
                float b0 = bias[n0 + cl], b1 = bias[n0 + cl + 1];
#pragma unroll
                for (int rr = 0; rr < 2; rr++) {
                    int rl = wm * 32 + mt * 16 + g + 8 * rr;
                    sv[rl * 68 + cl]     = d[mt][nt][2 * rr + 0] + b0;
                    sv[rl * 68 + cl + 1] = d[mt][nt][2 * rr + 1] + b1;
                }
            }
        }
        __syncthreads();
        const int bb = m0 >> 10, s0 = m0 & 1023, head = n0 >> 6;
        const int zv = bb * 8 + head;
        const int dd = tid & 63, sg = tid >> 6;
        ll base = ((ll)zv * 64 + dd) * 512 + ((s0 + sg * 32) >> 1);
#pragma unroll
        for (int j = 0; j < 16; j++)
            VTh[base + j] = pack_f16(sv[(sg * 32 + 2 * j) * 68 + dd],
                                     sv[(sg * 32 + 2 * j + 1) * 68 + dd]);
        return;
    }

    if (EPACK == 3) {
        __half* Cz = (__half*)C + (ll)b * sCb + (ll)h * sCh;
#pragma unroll
        for (int mt = 0; mt < 2; mt++) {
#pragma unroll
            for (int nt = 0; nt < 4; nt++) {
                int col = n0 + wn * 32 + nt * 8 + 2 * t;
#pragma unroll
                for (int rr = 0; rr < 2; rr++) {
                    int row = m0 + wm * 32 + mt * 16 + g + 8 * rr;
                    if (row >= M) continue;
                    float v0 = d[mt][nt][2 * rr + 0];
                    float v1 = d[mt][nt][2 * rr + 1];
                    if (col + 1 < N)
                        *(__half2*)(Cz + (ll)row * ldc + col) = __floats2half2_rn(v0, v1);
                    else if (col < N)
                        Cz[(ll)row * ldc + col] = __float2half(v0);
                }
            }
        }
        return;
    }

    float* Cz = C + (ll)b * sCb + (ll)h * sCh;
#pragma unroll
    for (int mt = 0; mt < 2; mt++) {
#pragma unroll
        for (int nt = 0; nt < 4; nt++) {
            int col = n0 + wn * 32 + nt * 8 + 2 * t;
            float b0 = (bias && col < N) ? bias[col] : 0.f;
            float b1 = (bias && col + 1 < N) ? bias[col + 1] : 0.f;
#pragma unroll
            for (int rr = 0; rr < 2; rr++) {
                int row = m0 + wm * 32 + mt * 16 + g + 8 * rr;
                if (row >= M) continue;
                float v0 = d[mt][nt][2 * rr + 0] + b0;
                float v1 = d[mt][nt][2 * rr + 1] + b1;
                if (col < N)     Cz[(ll)row * ldc + col]     = v0;
                if (col + 1 < N) Cz[(ll)row * ldc + col + 1] = v1;
                if (EPACK == 1 && h == 0) {
                    int tloc = row & 1023;
                    if (tloc >= 512) {
                        int zq = ((row >> 10) << 3) + (col >> 6);
                        ll qi = ((ll)zq * 512 + (tloc - 512)) * 32 + ((col & 63) >> 1);
                        split_pack(v0 + pbv[col], v1 + pbv[col + 1], QRh[qi], QRl[qi]);
                    }
                }
            }
        }
    }
}

// ---------------- fused flash attention: bf16x2 QK (3-term), fp16 PV (2-term), fp16 R ----------------
#define PSTR 36
#define FL_SMEM (6 * 2304 * 4)

__global__ void __launch_bounds__(128, 4) flash_attn(
    const float* __restrict__ Q,
    const unsigned int* __restrict__ Kph, const unsigned int* __restrict__ Kpl,
    const unsigned int* __restrict__ VTh,
    const float* __restrict__ pbu, const __half* __restrict__ Rr,
    const unsigned int* __restrict__ mbits,
    unsigned int* __restrict__ Oph, unsigned int* __restrict__ Opl)
{
    extern __shared__ uint32_t smu[];
    uint32_t* VH = smu + 4 * 2304;

    const int z = blockIdx.y, b = z >> 3, h = z & 7;
    const int t0 = blockIdx.x * 64;
    const int tid = threadIdx.x, lane = tid & 31, w = tid >> 5;
    const int g = lane >> 2, t = lane & 3;
    const int grp = lane >> 3, gi = lane & 7;

    const float* Qb = Q + ((ll)(b * TT + t0)) * DM + h * DK;
    const ll rb = (ll)z * 512 * RSTR;

    uint32_t qh[4][4], ql[4][4];
    {
        const int r0 = w * 16 + g, r1 = r0 + 8;
#pragma unroll
        for (int ks = 0; ks < 4; ks++) {
#pragma unroll
            for (int half = 0; half < 2; half++) {
                int c = 16 * ks + 8 * half + 2 * t;
                float u0 = pbu[h * DK + c], u1 = pbu[h * DK + c + 1];
                float x0 = Qb[(ll)r0 * DM + c] + u0;
                float x1 = Qb[(ll)r0 * DM + c + 1] + u1;
                float y0 = Qb[(ll)r1 * DM + c] + u0;
                float y1 = Qb[(ll)r1 * DM + c + 1] + u1;
                split_pack(x0, x1, qh[ks][2 * half + 0], ql[ks][2 * half + 0]);
                split_pack(y0, y1, qh[ks][2 * half + 1], ql[ks][2 * half + 1]);
            }
        }
    }

    float o[8][4];
#pragma unroll
    for (int i = 0; i < 8; i++)
#pragma unroll
        for (int j = 0; j < 4; j++) o[i][j] = 0.f;
    float mx0 = -1e30f, mx1 = -1e30f, l0 = 0.f, l1 = 0.f;

    uint32_t sBase = (uint32_t)__cvta_generic_to_shared(smu);

    auto loadKV = [&](int st, int buf) {
        const unsigned int* kh = Kph + ((ll)z * 1024 + st * 64) * 32;
        const unsigned int* kl = Kpl + ((ll)z * 1024 + st * 64) * 32;
        const unsigned int* vh = VTh + (ll)z * 64 * 512 + st * 32;
        uint32_t o0 = sBase + (uint32_t)(buf * 2304) * 4;
#pragma unroll
        for (int i = 0; i < 4; i++) {
            int idx = tid + 128 * i;
            int row = idx >> 3, c4 = (idx & 7) << 2;
            uint32_t soff = (uint32_t)(row * PSTR + c4) * 4;
            cp_async16(o0 + soff,                kh + (ll)row * 32 + c4, true);
            cp_async16(o0 + 2 * 2304 * 4 + soff, kl + (ll)row * 32 + c4, true);
            cp_async16(o0 + 4 * 2304 * 4 + soff, vh + (ll)row * 512 + c4, true);
        }
    };

    loadKV(0, 0);
    cp_commit();

    const int tg0 = t0 + w * 16 + g, tg1 = tg0 + 8;
    const __half2* R0 = (const __half2*)(Rr + rb + (ll)(tg0 >> 1) * RSTR);
    const __half2* R1 = (const __half2*)(Rr + rb + (ll)(tg1 >> 1) * RSTR);
    const int p0 = (tg0 & 1) << 10, p1 = (tg1 & 1) << 10;
    const uint2* mrow0 = (const uint2*)(mbits + ((ll)b * TT + tg0) * 32);
    const uint2* mrow1 = (const uint2*)(mbits + ((ll)b * TT + tg1) * 32);

    for (int st = 0; st < 16; st++) {
        const int buf = st & 1;
        cp_wait<0>();
        __syncthreads();
        if (st + 1 < 16) { loadKV(st + 1, 1 - buf); cp_commit(); }

        const uint32_t kAddr = sBase +
            (uint32_t)((((grp < 2 ? buf : 2 + buf) * 2304) + gi * PSTR + ((grp & 1) << 2)) << 2);
        const uint32_t* pVH = VH + buf * 2304;

        float sc[8][4];
#pragma unroll
        for (int i = 0; i < 8; i++)
#pragma unroll
            for (int j = 0; j < 4; j++) sc[i][j] = 0.f;
#pragma unroll
        for (int nt = 0; nt < 8; nt++) {
#pragma unroll
            for (int ks = 0; ks < 4; ks++) {
                uint32_t b0h, b1h, b0l, b1l;
                ldsm_x4(b0h, b1h, b0l, b1l, kAddr + (uint32_t)((nt * 8 * PSTR + 8 * ks) << 2));
                mma_bf16(sc[nt], qh[ks], b0h, b1h);
                mma_bf16(sc[nt], ql[ks], b0h, b1h);
                mma_bf16(sc[nt], qh[ks], b0l, b1l);
            }
        }

        const int s0 = st * 64;
#pragma unroll
        for (int nt = 0; nt < 8; nt++) {
            int s_ = s0 + nt * 8 + 2 * t;
            int la = s_ + p0, lb = s_ + p1;
            float2 va = __half22float2(R0[la >> 1]);
            float2 vb = __half22float2(R1[lb >> 1]);
            float pa1 = (la + 1 == LL) ? 0.f : va.y;
            float pb1 = (lb + 1 == LL) ? 0.f : vb.y;
            sc[nt][0] = (sc[nt][0] + va.x) * 0.125f;
            sc[nt][1] = (sc[nt][1] + pa1) * 0.125f;
            sc[nt][2] = (sc[nt][2] + vb.x) * 0.125f;
            sc[nt][3] = (sc[nt][3] + pb1) * 0.125f;
        }
        {
            uint2 w0 = mrow0[st], w1 = mrow1[st];
            u64 m0 = (u64)w0.x | ((u64)w0.y << 32);
            u64 m1 = (u64)w1.x | ((u64)w1.y << 32);
            if (m0 | m1) {
#pragma unroll
                for (int nt = 0; nt < 8; nt++) {
                    int p = nt * 8 + 2 * t;
                    if ((m0 >> p) & 1)       sc[nt][0] = -1e9f;
                    if ((m0 >> (p + 1)) & 1) sc[nt][1] = -1e9f;
                    if ((m1 >> p) & 1)       sc[nt][2] = -1e9f;
                    if ((m1 >> (p + 1)) & 1) sc[nt][3] = -1e9f;
                }
            }
        }

        float rmx0 = -1e30f, rmx1 = -1e30f;
#pragma unroll
        for (int nt = 0; nt < 8; nt++) {
            rmx0 = fmaxf(rmx0, fmaxf(sc[nt][0], sc[nt][1]));
            rmx1 = fmaxf(rmx1, fmaxf(sc[nt][2], sc[nt][3]));
        }
        rmx0 = fmaxf(rmx0, __shfl_xor_sync(0xffffffffu, rmx0, 1));
        rmx0 = fmaxf(rmx0, __shfl_xor_sync(0xffffffffu, rmx0, 2));
        rmx1 = fmaxf(rmx1, __shfl_xor_sync(0xffffffffu, rmx1, 1));
        rmx1 = fmaxf(rmx1, __shfl_xor_sync(0xffffffffu, rmx1, 2));

        float mn0 = fmaxf(mx0, rmx0), mn1 = fmaxf(mx1, rmx1);
        float al0 = __expf(mx0 - mn0), al1 = __expf(mx1 - mn1);
        float rs0 = 0.f, rs1 = 0.f;
#pragma unroll
        for (int nt = 0; nt < 8; nt++) {
            sc[nt][0] = __expf(sc[nt][0] - mn0);
            sc[nt][1] = __expf(sc[nt][1] - mn0);
            sc[nt][2] = __expf(sc[nt][2] - mn1);
            sc[nt][3] = __expf(sc[nt][3] - mn1);
            rs0 += sc[nt][0] + sc[nt][1];
            rs1 += sc[nt][2] + sc[nt][3];
        }
        rs0 += __shfl_xor_sync(0xffffffffu, rs0, 1);
        rs0 += __shfl_xor_sync(0xffffffffu, rs0, 2);
        rs1 += __shfl_xor_sync(0xffffffffu, rs1, 1);
        rs1 += __shfl_xor_sync(0xffffffffu, rs1, 2);
        l0 = l0 * al0 + rs0;
        l1 = l1 * al1 + rs1;
        mx0 = mn0; mx1 = mn1;
#pragma unroll
        for (int dt = 0; dt < 8; dt++) {
            o[dt][0] *= al0; o[dt][1] *= al0;
            o[dt][2] *= al1; o[dt][3] *= al1;
        }

        // ---- O += P @ V : fp16 2-term ----
#pragma unroll
        for (int j = 0; j < 4; j++) {
            uint32_t aPh[4], aPl[4];
            split_pack_f16(sc[2 * j][0],     sc[2 * j][1],     aPh[0], aPl[0]);
            split_pack_f16(sc[2 * j][2],     sc[2 * j][3],     aPh[1], aPl[1]);
            split_pack_f16(sc[2 * j + 1][0], sc[2 * j + 1][1], aPh[2], aPl[2]);
            split_pack_f16(sc[2 * j + 1][2], sc[2 * j + 1][3], aPh[3], aPl[3]);
#pragma unroll
            for (int dt = 0; dt < 8; dt++) {
                const int vrow = (dt * 8 + g) * PSTR;
                uint32_t b0h = pVH[vrow + 8 * j + t];
                uint32_t b1h = pVH[vrow + 8 * j + 4 + t];
                mma_f16(o[dt], aPh, b0h, b1h);
                mma_f16(o[dt], aPl, b0h, b1h);
            }
        }
    }

    float inv0 = 1.f / l0, inv1 = 1.f / l1;
    ll base0 = ((ll)(b * TT + tg0)) * 256 + h * 32;
    ll base1 = ((ll)(b * TT + tg1)) * 256 + h * 32;
#pragma unroll
    for (int dt = 0; dt < 8; dt++) {
        int pj = dt * 4 + t;
        split_pack(o[dt][0] * inv0, o[dt][1] * inv0, Oph[base0 + pj], Opl[base0 + pj]);
        split_pack(o[dt][2] * inv1, o[dt][3] * inv1, Oph[base1 + pj], Opl[base1 + pj]);
    }
}

// ---------------- launch ----------------
extern "C" void kernel_launch(void* const* d_in, const int* in_sizes, int n_in,
                              void* d_out, int out_size)
{
    const float* x   = (const float*)d_in[0];
    const float* pos = (const float*)d_in[1];
    const unsigned char* mask = (const unsigned char*)d_in[2];
    const float* Wq = (const float*)d_in[3];  const float* bq = (const float*)d_in[4];
    const float* Wk = (const float*)d_in[5];  const float* bk = (const float*)d_in[6];
    const float* Wv = (const float*)d_in[7];  const float* bv = (const float*)d_in[8];
    const float* Wp = (const float*)d_in[9];  const float* bp = (const float*)d_in[10];
    const float* Wo = (const float*)d_in[11]; const float* bo = (const float*)d_in[12];
    const float* pbu = (const float*)d_in[13];
    const float* pbv = (const float*)d_in[14];
    float* out = (float*)d_out;

    float *QKV;
    __half* Rh;
    unsigned int *Mb, *Kph, *Kpl, *VTh;
    unsigned int *xph, *xpl, *pph, *ppl, *Pph, *Ppl, *QRh, *QRl, *Oph, *Opl;
    unsigned int *Wqkvh, *Wqkvl, *Wph_, *Wpl_, *Woh, *Wol;
    cudaGetSymbolAddress((void**)&QKV, g_QKV);
    cudaGetSymbolAddress((void**)&Rh, g_Rh);
    cudaGetSymbolAddress((void**)&Mb, g_Mb);
    cudaGetSymbolAddress((void**)&Kph, g_Kph);
    cudaGetSymbolAddress((void**)&Kpl, g_Kpl);
    cudaGetSymbolAddress((void**)&VTh, g_VTh);
    cudaGetSymbolAddress((void**)&xph, g_xph);
    cudaGetSymbolAddress((void**)&xpl, g_xpl);
    cudaGetSymbolAddress((void**)&pph, g_pph);
    cudaGetSymbolAddress((void**)&ppl, g_ppl);
    cudaGetSymbolAddress((void**)&Pph, g_Pph);
    cudaGetSymbolAddress((void**)&Ppl, g_Ppl);
    cudaGetSymbolAddress((void**)&QRh, g_QRh);
    cudaGetSymbolAddress((void**)&QRl, g_QRl);
    cudaGetSymbolAddress((void**)&Oph, g_Oph);
    cudaGetSymbolAddress((void**)&Opl, g_Opl);
    cudaGetSymbolAddress((void**)&Wqkvh, g_Wqkvh);
    cudaGetSymbolAddress((void**)&Wqkvl, g_Wqkvl);
    cudaGetSymbolAddress((void**)&Wph_, g_Wph);
    cudaGetSymbolAddress((void**)&Wpl_, g_Wpl);
    cudaGetSymbolAddress((void**)&Woh, g_Woh);
    cudaGetSymbolAddress((void**)&Wol, g_Wol);

    cudaFuncSetAttribute((const void*)bf16_gemm<0, 0>, cudaFuncAttributeMaxDynamicSharedMemorySize, G2_SMEM);
    cudaFuncSetAttribute((const void*)bf16_gemm<0, 1>, cudaFuncAttributeMaxDynamicSharedMemorySize, G2_SMEM);
    cudaFuncSetAttribute((const void*)bf16_gemm<0, 2>, cudaFuncAttributeMaxDynamicSharedMemorySize, G2_SMEM);
    cudaFuncSetAttribute((const void*)bf16_gemm<1, 3>, cudaFuncAttributeMaxDynamicSharedMemorySize, G2_SMEM);
    cudaFuncSetAttribute((const void*)flash_attn, cudaFuncAttributeMaxDynamicSharedMemorySize, FL_SMEM);

    dim3 blk(256);

    // 1) all independent packs
    megapack1<<<dim3(4096, 1, 8), blk>>>(
        x, pos, mask, Wq, Wk, Wv, Wp, Wo,
        Wqkvh, Wqkvl, Wph_, Wpl_, Woh, Wol, xph, xpl, pph, ppl, Mb);

    // 2) fused Q/K/V projection:
    //    h==0: fp32 Q + QR pack (rows>=512); h==1: packed K; h==2: transposed fp16 V
    bf16_gemm<0, 1><<<dim3(8, 32, 3), blk, G2_SMEM>>>(
        xph, xpl, 256, 0, 0,
        Wqkvh, Wqkvl, 512, 0, 131072,
        QKV, DM, 0, 2097152,
        NB * TT, DM, 256, bq, bk, bv, Kph, Kpl, pbv, QRh, QRl, VTh);

    // 3) P projection -> packed Pph/Ppl directly
    bf16_gemm<0, 2><<<dim3(8, 16, 1), blk, G2_SMEM>>>(
        pph, ppl, 256, 0, 0, Wph_, Wpl_, 512, 0, 0,
        nullptr, DM, 0, 0, LL, DM, 256, bp, bp, bp, Pph, Ppl, nullptr, nullptr, nullptr, nullptr);

    // 4) R = (Q[512:]+pbv) @ P^T per (b,h), fp16 output
    bf16_gemm<1, 3><<<dim3(32, 4, 32), blk, G2_SMEM>>>(
        QRh, QRl, 32, 8LL * 512 * 32, 512 * 32,
        Pph, Ppl, 256, 0, 32,
        (float*)Rh, RSTR, 8LL * 512 * RSTR, (ll)512 * RSTR,
        512, LL, 32, nullptr, nullptr, nullptr, nullptr, nullptr, nullptr, nullptr, nullptr, nullptr);

    // 5) flash attention (fp16 R)
    flash_attn<<<dim3(16, 32), dim3(128), FL_SMEM>>>(
        QKV, Kph, Kpl, VTh, pbu, Rh, Mb, Oph, Opl);

    // 6) out = O @ Wo + bo
    bf16_gemm<0, 0><<<dim3(8, 32, 1), blk, G2_SMEM>>>(
        Oph, Opl, 256, 0, 0, Woh, Wol, 512, 0, 0,
        out, DM, 0, 0, NB * TT, DM, 256, bo, bo, bo, nullptr, nullptr, nullptr, nullptr, nullptr, nullptr);
}

// round 17
// speedup vs baseline: 1.6278x; 1.0626x over previous
#include <cuda_runtime.h>
#include <cuda_bf16.h>
#include <cuda_fp16.h>
#include <cstdint>

#define TT 1024
#define DM 512
#define NB 4
#define NH 8
#define DK 64
#define LL 2047   // 2*T - 1
#define RSTR 2048
typedef long long ll;
typedef unsigned long long u64;

// ---------------- scratch ----------------
__device__ float g_QKV[3LL * NB * TT * DM];     // Q | (K,V unused)
__device__ __half g_Rh[32LL * 512 * RSTR];      // R in fp16
__device__ unsigned int g_Mb[NB * TT * 32];
__device__ unsigned int g_Kph[32LL * 1024 * 32];
__device__ unsigned int g_Kpl[32LL * 1024 * 32];
__device__ unsigned int g_VTh[32LL * 64 * 512];   // fp16x2 pairs along s
__device__ unsigned int g_xph[NB * TT * 256],  g_xpl[NB * TT * 256];
__device__ unsigned int g_pph[2047 * 256],     g_ppl[2047 * 256];
__device__ unsigned int g_Wqkvh[3 * 256 * 512], g_Wqkvl[3 * 256 * 512];
__device__ unsigned int g_Wph[256 * 512], g_Wpl[256 * 512];
__device__ unsigned int g_Woh[256 * 512], g_Wol[256 * 512];
__device__ unsigned int g_Pph[2047 * 256], g_Ppl[2047 * 256];
__device__ unsigned int g_QRh[32LL * 512 * 32], g_QRl[32LL * 512 * 32];
__device__ unsigned int g_Oph[NB * TT * 256], g_Opl[NB * TT * 256];

// ---------------- helpers ----------------
__device__ __forceinline__ float bf16_hi(float x) {
    return __bfloat162float(__float2bfloat16(x));
}
__device__ __forceinline__ uint32_t pack_bf16(float lo_elem, float hi_elem) {
    uint32_t r;
    asm("cvt.rn.bf16x2.f32 %0, %1, %2;" : "=r"(r) : "f"(hi_elem), "f"(lo_elem));
    return r;
}
__device__ __forceinline__ void split_pack(float a, float b, uint32_t& ph, uint32_t& pl) {
    float ha = bf16_hi(a), hb = bf16_hi(b);
    ph = pack_bf16(a, b);
    pl = pack_bf16(a - ha, b - hb);
}
__device__ __forceinline__ float f16_hi(float x) {
    return __half2float(__float2half_rn(x));
}
__device__ __forceinline__ uint32_t pack_f16(float lo_elem, float hi_elem) {
    uint32_t r;
    asm("cvt.rn.f16x2.f32 %0, %1, %2;" : "=r"(r) : "f"(hi_elem), "f"(lo_elem));
    return r;
}
__device__ __forceinline__ void split_pack_f16(float a, float b, uint32_t& ph, uint32_t& pl) {
    float ha = f16_hi(a), hb = f16_hi(b);
    ph = pack_f16(a, b);
    pl = pack_f16(a - ha, b - hb);
}
__device__ __forceinline__ void mma_bf16(float* d, const uint32_t* a, uint32_t b0, uint32_t b1) {
    asm volatile(
        "mma.sync.aligned.m16n8k16.row.col.f32.bf16.bf16.f32 "
        "{%0,%1,%2,%3}, {%4,%5,%6,%7}, {%8,%9}, {%0,%1,%2,%3};\n"
        : "+f"(d[0]), "+f"(d[1]), "+f"(d[2]), "+f"(d[3])
        : "r"(a[0]), "r"(a[1]), "r"(a[2]), "r"(a[3]), "r"(b0), "r"(b1));
}
__device__ __forceinline__ void mma_f16(float* d, const uint32_t* a, uint32_t b0, uint32_t b1) {
    asm volatile(
        "mma.sync.aligned.m16n8k16.row.col.f32.f16.f16.f32 "
        "{%0,%1,%2,%3}, {%4,%5,%6,%7}, {%8,%9}, {%0,%1,%2,%3};\n"
        : "+f"(d[0]), "+f"(d[1]), "+f"(d[2]), "+f"(d[3])
        : "r"(a[0]), "r"(a[1]), "r"(a[2]), "r"(a[3]), "r"(b0), "r"(b1));
}
__device__ __forceinline__ void ldsm_x4(uint32_t& r0, uint32_t& r1, uint32_t& r2, uint32_t& r3,
                                        uint32_t addr) {
    asm volatile("ldmatrix.sync.aligned.m8n8.x4.shared.b16 {%0,%1,%2,%3}, [%4];\n"
                 : "=r"(r0), "=r"(r1), "=r"(r2), "=r"(r3) : "r"(addr));
}
__device__ __forceinline__ void cp_async16(uint32_t dst, const void* src, bool p) {
    asm volatile("cp.async.cg.shared.global [%0], [%1], 16, %2;\n"
                 :: "r"(dst), "l"(src), "r"(p ? 16 : 0));
}
__device__ __forceinline__ void cp_commit() { asm volatile("cp.async.commit_group;\n"); }
template <int N>
__device__ __forceinline__ void cp_wait() { asm volatile("cp.async.wait_group %0;\n" :: "n"(N)); }

// ---------------- mega-pack 1: all input-only packs, grid (4096,1,8) ----------------
__global__ void __launch_bounds__(256) megapack1(
    const float* __restrict__ x, const float* __restrict__ pos,
    const unsigned char* __restrict__ mask,
    const float* __restrict__ Wq, const float* __restrict__ Wk,
    const float* __restrict__ Wv, const float* __restrict__ Wp,
    const float* __restrict__ Wo,
    unsigned int* __restrict__ Wqkvh, unsigned int* __restrict__ Wqkvl,
    unsigned int* __restrict__ Wph, unsigned int* __restrict__ Wpl,
    unsigned int* __restrict__ Woh, unsigned int* __restrict__ Wol,
    unsigned int* __restrict__ xph, unsigned int* __restrict__ xpl,
    unsigned int* __restrict__ pph, unsigned int* __restrict__ ppl,
    unsigned int* __restrict__ Mb)
{
    const int zz = blockIdx.z, bx = blockIdx.x, tid = threadIdx.x;
    if (zz < 5) {
        if (bx >= 512) return;
        int i = bx * 256 + tid;
        int r = i >> 9, n = i & 511;
        const float* W = zz == 0 ? Wq : zz == 1 ? Wk : zz == 2 ? Wv : zz == 3 ? Wp : Wo;
        unsigned int *ph, *pl;
        if (zz < 3)      { ph = Wqkvh + zz * 131072; pl = Wqkvl + zz * 131072; }
        else if (zz == 3){ ph = Wph; pl = Wpl; }
        else             { ph = Woh; pl = Wol; }
        split_pack(W[(2 * r) * 512 + n], W[(2 * r + 1) * 512 + n], ph[i], pl[i]);
    } else if (zz == 5) {
        ll i = (ll)bx * 256 + tid;
        float2 v = *(const float2*)(x + 2 * i);
        split_pack(v.x, v.y, xph[i], xpl[i]);
    } else if (zz == 6) {
        if (bx >= 2047) return;
        ll i = (ll)bx * 256 + tid;
        float2 v = *(const float2*)(pos + 2 * i);
        split_pack(v.x, v.y, pph[i], ppl[i]);
    } else {
        if (bx >= 512) return;
        int i = bx * 256 + tid;
        const uchar4* p = (const uchar4*)(mask + (ll)i * 32);
        unsigned int bits = 0;
#pragma unroll
        for (int j = 0; j < 8; j++) {
            uchar4 v = p[j];
            unsigned int q = (v.x ? 1u : 0u) | (v.y ? 2u : 0u) | (v.z ? 4u : 0u) | (v.w ? 8u : 0u);
            bits |= q << (4 * j);
        }
        Mb[i] = bits;
    }
}

// ---------------- bf16x2 pipelined GEMM (ldmatrix fragments) ----------------
// EPACK=0: fp32 C.
// EPACK=1 (mega): h==0 fp32 Q + QR pack; h==1 packed K; h==2 V transpose-pack;
//                 h==3 P projection (A=pos pairs, B=Wp, M=LL) -> packed P pairs.
// EPACK=3: fp16 C.
#define A_STR 20
#define BN_STR 72
#define BT_STR 20
#define G2_SMEM ((4 * 2560 + 4 * 1280) * 4)

template <int TRANSB, int EPACK>
__global__ void __launch_bounds__(256) bf16_gemm(
    const unsigned int* __restrict__ Aph, const unsigned int* __restrict__ Apl,
    int ldap, ll sAb, ll sAh,
    const unsigned int* __restrict__ Bph, const unsigned int* __restrict__ Bpl,
    int ldbp, ll sBb, ll sBh,
    float* __restrict__ C, int ldc, ll sCb, ll sCh,
    int M, int N, int Kp,
    const float* __restrict__ bias0, const float* __restrict__ bias1,
    const float* __restrict__ bias2,
    unsigned int* __restrict__ Ph, unsigned int* __restrict__ Pl,
    const float* __restrict__ pbv,
    unsigned int* __restrict__ QRh, unsigned int* __restrict__ QRl,
    unsigned int* __restrict__ VTh,
    const unsigned int* __restrict__ A3h, const unsigned int* __restrict__ A3l,
    const unsigned int* __restrict__ WpH, const unsigned int* __restrict__ WpL,
    const float* __restrict__ bias3,
    unsigned int* __restrict__ P2h, unsigned int* __restrict__ P2l)
{
    extern __shared__ uint32_t su[];
    uint32_t* BH = su + 10240;
    uint32_t* BLo = su + 12800;

    const int z = blockIdx.z, b = z >> 3, h = z & 7;
    const bool isP = (EPACK == 1 && h == 3);
    if (isP && blockIdx.y >= 16) return;
    const int Mm = isP ? LL : M;
    const float* bias = (h == 0) ? bias0 : (h == 1) ? bias1 : (h == 2) ? bias2 : bias3;
    Aph += (ll)b * sAb + (ll)h * sAh;
    Apl += (ll)b * sAb + (ll)h * sAh;
    if (!isP) {
        Bph += (ll)b * sBb + (ll)h * sBh;
        Bpl += (ll)b * sBb + (ll)h * sBh;
    } else {
        Aph = A3h; Apl = A3l;
        Bph = WpH; Bpl = WpL;
    }

    const int tid = threadIdx.x;
    const int lane = tid & 31, wid = tid >> 5;
    const int g = lane >> 2, t = lane & 3;
    const int grp = lane >> 3, gi = lane & 7;
    const int wm = wid & 3, wn = wid >> 2;
    const int m0 = blockIdx.y * 128, n0 = blockIdx.x * 64;

    uint32_t sBase = (uint32_t)__cvta_generic_to_shared(su);

    auto stage = [&](int k0p, int stg) {
#pragma unroll
        for (int i = 0; i < 2; i++) {
            int idx = tid + 256 * i;
            int row = idx >> 2, c4 = (idx & 3) << 2;
            bool p = (m0 + row) < Mm;
            const ll off = (ll)(m0 + row) * ldap + k0p + c4;
            uint32_t d0 = sBase + (uint32_t)(stg * 2560 + row * A_STR + c4) * 4;
            cp_async16(d0, Aph + off, p);
            cp_async16(d0 + 5120 * 4, Apl + off, p);
        }
        if (!TRANSB) {
            int row = tid >> 4, c4 = (tid & 15) << 2;
            const ll off = (ll)(k0p + row) * ldbp + n0 + c4;
            uint32_t d0 = sBase + (uint32_t)(10240 + stg * 1280 + row * BN_STR + c4) * 4;
            cp_async16(d0, Bph + off, true);
            cp_async16(d0 + 2560 * 4, Bpl + off, true);
        } else {
            int row = tid >> 2, c4 = (tid & 3) << 2;
            bool p = (n0 + row) < N;
            const ll off = (ll)(n0 + row) * ldbp + k0p + c4;
            uint32_t d0 = sBase + (uint32_t)(10240 + stg * 1280 + row * BT_STR + c4) * 4;
            cp_async16(d0, Bph + off, p);
            cp_async16(d0 + 2560 * 4, Bpl + off, p);
        }
    };

    float d[2][4][4];
#pragma unroll
    for (int i = 0; i < 2; i++)
#pragma unroll
        for (int j = 0; j < 4; j++)
#pragma unroll
            for (int c = 0; c < 4; c++) d[i][j][c] = 0.f;

    const int nIter = Kp >> 4;
    stage(0, 0);
    cp_commit();

    for (int it = 0; it < nIter; it++) {
        __syncthreads();
        if (it + 1 < nIter) { stage((it + 1) << 4, (it + 1) & 1); cp_commit(); cp_wait<1>(); }
        else cp_wait<0>();
        __syncthreads();

        const uint32_t aBaseH = sBase +
            (uint32_t)(((it & 1) * 2560 + (wm * 32 + ((grp & 1) << 3) + gi) * A_STR + ((grp >> 1) << 2)) << 2);
        const uint32_t aBaseL = aBaseH + (5120u << 2);
        uint32_t bBaseT = 0;
        if (TRANSB)
            bBaseT = sBase + (uint32_t)((10240 + (grp < 2 ? 0 : 2560) + (it & 1) * 1280 +
                                         (wn * 32 + gi) * BT_STR + ((grp & 1) << 2)) << 2);
        const uint32_t* pBH = BH + (it & 1) * 1280;
        const uint32_t* pBL = BLo + (it & 1) * 1280;

#pragma unroll
        for (int ck = 0; ck < 2; ck++) {
            const int kb = ck * 8;
            uint32_t aH[2][4], aL[2][4];
#pragma unroll
            for (int mt = 0; mt < 2; mt++) {
                uint32_t off = (uint32_t)((mt * 16 * A_STR + kb) << 2);
                ldsm_x4(aH[mt][0], aH[mt][1], aH[mt][2], aH[mt][3], aBaseH + off);
                ldsm_x4(aL[mt][0], aL[mt][1], aL[mt][2], aL[mt][3], aBaseL + off);
            }
#pragma unroll
            for (int nt = 0; nt < 4; nt++) {
                uint32_t b0h, b1h, b0l, b1l;
                if (!TRANSB) {
                    int col = wn * 32 + nt * 8 + g;
                    int i0 = (kb + t) * BN_STR + col, i1 = (kb + t + 4) * BN_STR + col;
                    b0h = pBH[i0]; b1h = pBH[i1];
                    b0l = pBL[i0]; b1l = pBL[i1];
                } else {
                    ldsm_x4(b0h, b1h, b0l, b1l, bBaseT + (uint32_t)((nt * 8 * BT_STR + kb) << 2));
                }
#pragma unroll
                for (int mt = 0; mt < 2; mt++) {
                    mma_bf16(d[mt][nt], aH[mt], b0h, b1h);
                    mma_bf16(d[mt][nt], aL[mt], b0h, b1h);
                    mma_bf16(d[mt][nt], aH[mt], b0l, b1l);
                }
            }
        }
    }

    // ---- epilogue ----
    if (isP) {
        // P projection slab: packed bf16 hi/lo pairs (pairs along d = column pairs)
#pragma unroll
        for (int mt = 0; mt < 2; mt++) {
#pragma unroll
            for (int nt = 0; nt < 4; nt++) {
                int col = n0 + wn * 32 + nt * 8 + 2 * t;
                float b0 = bias[col], b1 = bias[col + 1];
#pragma unroll
                for (int rr = 0; rr < 2; rr++) {
                    int row = m0 + wm * 32 + mt * 16 + g + 8 * rr;
                    if (row >= Mm) continue;
                    float v0 = d[mt][nt][2 * rr + 0] + b0;
                    float v1 = d[mt][nt][2 * rr + 1] + b1;
                    ll idx = (ll)row * 256 + (col >> 1);
                    split_pack(v0, v1, P2h[idx], P2l[idx]);
                }
            }
        }
        return;
    }

    const bool packK = (EPACK == 1 && h == 1);
    if (packK) {
#pragma unroll
        for (int mt = 0; mt < 2; mt++) {
#pragma unroll
            for (int nt = 0; nt < 4; nt++) {
                int col = n0 + wn * 32 + nt * 8 + 2 * t;
                float b0 = bias[col], b1 = bias[col + 1];
#pragma unroll
                for (int rr = 0; rr < 2; rr++) {
                    int row = m0 + wm * 32 + mt * 16 + g + 8 * rr;
                    if (row >= Mm) continue;
                    float v0 = d[mt][nt][2 * rr + 0] + b0;
                    float v1 = d[mt][nt][2 * rr + 1] + b1;
                    int zk = ((row >> 10) << 3) + (col >> 6);
                    ll idx = ((ll)zk * 1024 + (row & 1023)) * 32 + ((col & 63) >> 1);
                    split_pack(v0, v1, Ph[idx], Pl[idx]);
                }
            }
        }
        return;
    }

    if (EPACK == 1 && h == 2) {
        // V slab: transpose-pack to VTh via smem staging (fp16 pairs along s)
        float* sv = (float*)su;   // [128][68]
        __syncthreads();
#pragma unroll
        for (int mt = 0; mt < 2; mt++) {
#pragma unroll
            for (int nt = 0; nt < 4; nt++) {
                int cl = wn * 32 + nt * 8 + 2 * t;
                float b0 = bias[n0 + cl], b1 = bias[n0 + cl + 1];
#pragma unroll
                for (int rr = 0; rr < 2; rr++) {
                    int rl = wm * 32 + mt * 16 + g + 8 * rr;
                    sv[rl * 68 + cl]     = d[mt][nt][2 * rr + 0] + b0;
                    sv[rl * 68 + cl + 1] = d[mt][nt][2 * rr + 1] + b1;
                }
            }
        }
        __syncthreads();
        const int bb = m0 >> 10, s0 = m0 & 1023, head = n0 >> 6;
        const int zv = bb * 8 + head;
        const int dd = tid & 63, sg = tid >> 6;
        ll base = ((ll)zv * 64 + dd) * 512 + ((s0 + sg * 32) >> 1);
#pragma unroll
        for (int j = 0; j < 16; j++)
            VTh[base + j] = pack_f16(sv[(sg * 32 + 2 * j) * 68 + dd],
                                     sv[(sg * 32 + 2 * j + 1) * 68 + dd]);
        return;
    }

    if (EPACK == 3) {
        __half* Cz = (__half*)C + (ll)b * sCb + (ll)h * sCh;
#pragma unroll
        for (int mt = 0; mt < 2; mt++) {
#pragma unroll
            for (int nt = 0; nt < 4; nt++) {
                int col = n0 + wn * 32 + nt * 8 + 2 * t;
#pragma unroll
                for (int rr = 0; rr < 2; rr++) {
                    int row = m0 + wm * 32 + mt * 16 + g + 8 * rr;
                    if (row >= Mm) continue;
                    float v0 = d[mt][nt][2 * rr + 0];
                    float v1 = d[mt][nt][2 * rr + 1];
                    if (col + 1 < N)
                        *(__half2*)(Cz + (ll)row * ldc + col) = __floats2half2_rn(v0, v1);
                    else if (col < N)
                        Cz[(ll)row * ldc + col] = __float2half(v0);
                }
            }
        }
        return;
    }

    float* Cz = C + (ll)b * sCb + (ll)h * sCh;
#pragma unroll
    for (int mt = 0; mt < 2; mt++) {
#pragma unroll
        for (int nt = 0; nt < 4; nt++) {
            int col = n0 + wn * 32 + nt * 8 + 2 * t;
            float b0 = (bias && col < N) ? bias[col] : 0.f;
            float b1 = (bias && col + 1 < N) ? bias[col + 1] : 0.f;
#pragma unroll
            for (int rr = 0; rr < 2; rr++) {
                int row = m0 + wm * 32 + mt * 16 + g + 8 * rr;
                if (row >= Mm) continue;
                float v0 = d[mt][nt][2 * rr + 0] + b0;
                float v1 = d[mt][nt][2 * rr + 1] + b1;
                if (col < N)     Cz[(ll)row * ldc + col]     = v0;
                if (col + 1 < N) Cz[(ll)row * ldc + col + 1] = v1;
                if (EPACK == 1 && h == 0) {
                    int tloc = row & 1023;
                    if (tloc >= 512) {
                        int zq = ((row >> 10) << 3) + (col >> 6);
                        ll qi = ((ll)zq * 512 + (tloc - 512)) * 32 + ((col & 63) >> 1);
                        split_pack(v0 + pbv[col], v1 + pbv[col + 1], QRh[qi], QRl[qi]);
                    }
                }
            }
        }
    }
}

// ---------------- fused flash attention: bf16x2 QK (3-term), fp16 PV (2-term), fp16 R ----------------
#define PSTR 36
#define FL_SMEM (6 * 2304 * 4)

__global__ void __launch_bounds__(128, 4) flash_attn(
    const float* __restrict__ Q,
    const unsigned int* __restrict__ Kph, const unsigned int* __restrict__ Kpl,
    const unsigned int* __restrict__ VTh,
    const float* __restrict__ pbu, const __half* __restrict__ Rr,
    const unsigned int* __restrict__ mbits,
    unsigned int* __restrict__ Oph, unsigned int* __restrict__ Opl)
{
    extern __shared__ uint32_t smu[];
    uint32_t* VH = smu + 4 * 2304;

    const int z = blockIdx.y, b = z >> 3, h = z & 7;
    const int t0 = blockIdx.x * 64;
    const int tid = threadIdx.x, lane = tid & 31, w = tid >> 5;
    const int g = lane >> 2, t = lane & 3;
    const int grp = lane >> 3, gi = lane & 7;

    const float* Qb = Q + ((ll)(b * TT + t0)) * DM + h * DK;
    const ll rb = (ll)z * 512 * RSTR;

    uint32_t qh[4][4], ql[4][4];
    {
        const int r0 = w * 16 + g, r1 = r0 + 8;
#pragma unroll
        for (int ks = 0; ks < 4; ks++) {
#pragma unroll
            for (int half = 0; half < 2; half++) {
                int c = 16 * ks + 8 * half + 2 * t;
                float u0 = pbu[h * DK + c], u1 = pbu[h * DK + c + 1];
                float x0 = Qb[(ll)r0 * DM + c] + u0;
                float x1 = Qb[(ll)r0 * DM + c + 1] + u1;
                float y0 = Qb[(ll)r1 * DM + c] + u0;
                float y1 = Qb[(ll)r1 * DM + c + 1] + u1;
                split_pack(x0, x1, qh[ks][2 * half + 0], ql[ks][2 * half + 0]);
                split_pack(y0, y1, qh[ks][2 * half + 1], ql[ks][2 * half + 1]);
            }
        }
    }

    float o[8][4];
#pragma unroll
    for (int i = 0; i < 8; i++)
#pragma unroll
        for (int j = 0; j < 4; j++) o[i][j] = 0.f;
    float mx0 = -1e30f, mx1 = -1e30f, l0 = 0.f, l1 = 0.f;

    uint32_t sBase = (uint32_t)__cvta_generic_to_shared(smu);

    auto loadKV = [&](int st, int buf) {
        const unsigned int* kh = Kph + ((ll)z * 1024 + st * 64) * 32;
        const unsigned int* kl = Kpl + ((ll)z * 1024 + st * 64) * 32;
        const unsigned int* vh = VTh + (ll)z * 64 * 512 + st * 32;
        uint32_t o0 = sBase + (uint32_t)(buf * 2304) * 4;
#pragma unroll
        for (int i = 0; i < 4; i++) {
            int idx = tid + 128 * i;
            int row = idx >> 3, c4 = (idx & 7) << 2;
            uint32_t soff = (uint32_t)(row * PSTR + c4) * 4;
            cp_async16(o0 + soff,                kh + (ll)row * 32 + c4, true);
            cp_async16(o0 + 2 * 2304 * 4 + soff, kl + (ll)row * 32 + c4, true);
            cp_async16(o0 + 4 * 2304 * 4 + soff, vh + (ll)row * 512 + c4, true);
        }
    };

    loadKV(0, 0);
    cp_commit();

    const int tg0 = t0 + w * 16 + g, tg1 = tg0 + 8;
    const __half2* R0 = (const __half2*)(Rr + rb + (ll)(tg0 >> 1) * RSTR);
    const __half2* R1 = (const __half2*)(Rr + rb + (ll)(tg1 >> 1) * RSTR);
    const int p0 = (tg0 & 1) << 10, p1 = (tg1 & 1) << 10;
    const uint2* mrow0 = (const uint2*)(mbits + ((ll)b * TT + tg0) * 32);
    const uint2* mrow1 = (const uint2*)(mbits + ((ll)b * TT + tg1) * 32);

    for (int st = 0; st < 16; st++) {
        const int buf = st & 1;
        cp_wait<0>();
        __syncthreads();
        if (st + 1 < 16) { loadKV(st + 1, 1 - buf); cp_commit(); }

        const uint32_t kAddr = sBase +
            (uint32_t)((((grp < 2 ? buf : 2 + buf) * 2304) + gi * PSTR + ((grp & 1) << 2)) << 2);
        const uint32_t* pVH = VH + buf * 2304;

        float sc[8][4];
#pragma unroll
        for (int i = 0; i < 8; i++)
#pragma unroll
            for (int j = 0; j < 4; j++) sc[i][j] = 0.f;
#pragma unroll
        for (int nt = 0; nt < 8; nt++) {
#pragma unroll
            for (int ks = 0; ks < 4; ks++) {
                uint32_t b0h, b1h, b0l, b1l;
                ldsm_x4(b0h, b1h, b0l, b1l, kAddr + (uint32_t)((nt * 8 * PSTR + 8 * ks) << 2));
                mma_bf16(sc[nt], qh[ks], b0h, b1h);
                mma_bf16(sc[nt], ql[ks], b0h, b1h);
                mma_bf16(sc[nt], qh[ks], b0l, b1l);
            }
        }

        const int s0 = st * 64;
#pragma unroll
        for (int nt = 0; nt < 8; nt++) {
            int s_ = s0 + nt * 8 + 2 * t;
            int la = s_ + p0, lb = s_ + p1;
            float2 va = __half22float2(R0[la >> 1]);
            float2 vb = __half22float2(R1[lb >> 1]);
            float pa1 = (la + 1 == LL) ? 0.f : va.y;
            float pb1 = (lb + 1 == LL) ? 0.f : vb.y;
            sc[nt][0] = (sc[nt][0] + va.x) * 0.125f;
            sc[nt][1] = (sc[nt][1] + pa1) * 0.125f;
            sc[nt][2] = (sc[nt][2] + vb.x) * 0.125f;
            sc[nt][3] = (sc[nt][3] + pb1) * 0.125f;
        }
        {
            uint2 w0 = mrow0[st], w1 = mrow1[st];
            u64 m0 = (u64)w0.x | ((u64)w0.y << 32);
            u64 m1 = (u64)w1.x | ((u64)w1.y << 32);
            if (m0 | m1) {
#pragma unroll
                for (int nt = 0; nt < 8; nt++) {
                    int p = nt * 8 + 2 * t;
                    if ((m0 >> p) & 1)       sc[nt][0] = -1e9f;
                    if ((m0 >> (p + 1)) & 1) sc[nt][1] = -1e9f;
                    if ((m1 >> p) & 1)       sc[nt][2] = -1e9f;
                    if ((m1 >> (p + 1)) & 1) sc[nt][3] = -1e9f;
                }
            }
        }

        float rmx0 = -1e30f, rmx1 = -1e30f;
#pragma unroll
        for (int nt = 0; nt < 8; nt++) {
            rmx0 = fmaxf(rmx0, fmaxf(sc[nt][0], sc[nt][1]));
            rmx1 = fmaxf(rmx1, fmaxf(sc[nt][2], sc[nt][3]));
        }
        rmx0 = fmaxf(rmx0, __shfl_xor_sync(0xffffffffu, rmx0, 1));
        rmx0 = fmaxf(rmx0, __shfl_xor_sync(0xffffffffu, rmx0, 2));
        rmx1 = fmaxf(rmx1, __shfl_xor_sync(0xffffffffu, rmx1, 1));
        rmx1 = fmaxf(rmx1, __shfl_xor_sync(0xffffffffu, rmx1, 2));

        float mn0 = fmaxf(mx0, rmx0), mn1 = fmaxf(mx1, rmx1);
        float al0 = __expf(mx0 - mn0), al1 = __expf(mx1 - mn1);
        float rs0 = 0.f, rs1 = 0.f;
#pragma unroll
        for (int nt = 0; nt < 8; nt++) {
            sc[nt][0] = __expf(sc[nt][0] - mn0);
            sc[nt][1] = __expf(sc[nt][1] - mn0);
            sc[nt][2] = __expf(sc[nt][2] - mn1);
            sc[nt][3] = __expf(sc[nt][3] - mn1);
            rs0 += sc[nt][0] + sc[nt][1];
            rs1 += sc[nt][2] + sc[nt][3];
        }
        rs0 += __shfl_xor_sync(0xffffffffu, rs0, 1);
        rs0 += __shfl_xor_sync(0xffffffffu, rs0, 2);
        rs1 += __shfl_xor_sync(0xffffffffu, rs1, 1);
        rs1 += __shfl_xor_sync(0xffffffffu, rs1, 2);
        l0 = l0 * al0 + rs0;
        l1 = l1 * al1 + rs1;
        mx0 = mn0; mx1 = mn1;
#pragma unroll
        for (int dt = 0; dt < 8; dt++) {
            o[dt][0] *= al0; o[dt][1] *= al0;
            o[dt][2] *= al1; o[dt][3] *= al1;
        }

        // ---- O += P @ V : fp16 2-term ----
#pragma unroll
        for (int j = 0; j < 4; j++) {
            uint32_t aPh[4], aPl[4];
            split_pack_f16(sc[2 * j][0],     sc[2 * j][1],     aPh[0], aPl[0]);
            split_pack_f16(sc[2 * j][2],     sc[2 * j][3],     aPh[1], aPl[1]);
            split_pack_f16(sc[2 * j + 1][0], sc[2 * j + 1][1], aPh[2], aPl[2]);
            split_pack_f16(sc[2 * j + 1][2], sc[2 * j + 1][3], aPh[3], aPl[3]);
#pragma unroll
            for (int dt = 0; dt < 8; dt++) {
                const int vrow = (dt * 8 + g) * PSTR;
                uint32_t b0h = pVH[vrow + 8 * j + t];
                uint32_t b1h = pVH[vrow + 8 * j + 4 + t];
                mma_f16(o[dt], aPh, b0h, b1h);
                mma_f16(o[dt], aPl, b0h, b1h);
            }
        }
    }

    float inv0 = 1.f / l0, inv1 = 1.f / l1;
    ll base0 = ((ll)(b * TT + tg0)) * 256 + h * 32;
    ll base1 = ((ll)(b * TT + tg1)) * 256 + h * 32;
#pragma unroll
    for (int dt = 0; dt < 8; dt++) {
        int pj = dt * 4 + t;
        split_pack(o[dt][0] * inv0, o[dt][1] * inv0, Oph[base0 + pj], Opl[base0 + pj]);
        split_pack(o[dt][2] * inv1, o[dt][3] * inv1, Oph[base1 + pj], Opl[base1 + pj]);
    }
}

// ---------------- launch ----------------
extern "C" void kernel_launch(void* const* d_in, const int* in_sizes, int n_in,
                              void* d_out, int out_size)
{
    const float* x   = (const float*)d_in[0];
    const float* pos = (const float*)d_in[1];
    const unsigned char* mask = (const unsigned char*)d_in[2];
    const float* Wq = (const float*)d_in[3];  const float* bq = (const float*)d_in[4];
    const float* Wk = (const float*)d_in[5];  const float* bk = (const float*)d_in[6];
    const float* Wv = (const float*)d_in[7];  const float* bv = (const float*)d_in[8];
    const float* Wp = (const float*)d_in[9];  const float* bp = (const float*)d_in[10];
    const float* Wo = (const float*)d_in[11]; const float* bo = (const float*)d_in[12];
    const float* pbu = (const float*)d_in[13];
    const float* pbv = (const float*)d_in[14];
    float* out = (float*)d_out;

    float *QKV;
    __half* Rh;
    unsigned int *Mb, *Kph, *Kpl, *VTh;
    unsigned int *xph, *xpl, *pph, *ppl, *Pph, *Ppl, *QRh, *QRl, *Oph, *Opl;
    unsigned int *Wqkvh, *Wqkvl, *Wph_, *Wpl_, *Woh, *Wol;
    cudaGetSymbolAddress((void**)&QKV, g_QKV);
    cudaGetSymbolAddress((void**)&Rh, g_Rh);
    cudaGetSymbolAddress((void**)&Mb, g_Mb);
    cudaGetSymbolAddress((void**)&Kph, g_Kph);
    cudaGetSymbolAddress((void**)&Kpl, g_Kpl);
    cudaGetSymbolAddress((void**)&VTh, g_VTh);
    cudaGetSymbolAddress((void**)&xph, g_xph);
    cudaGetSymbolAddress((void**)&xpl, g_xpl);
    cudaGetSymbolAddress((void**)&pph, g_pph);
    cudaGetSymbolAddress((void**)&ppl, g_ppl);
    cudaGetSymbolAddress((void**)&Pph, g_Pph);
    cudaGetSymbolAddress((void**)&Ppl, g_Ppl);
    cudaGetSymbolAddress((void**)&QRh, g_QRh);
    cudaGetSymbolAddress((void**)&QRl, g_QRl);
    cudaGetSymbolAddress((void**)&Oph, g_Oph);
    cudaGetSymbolAddress((void**)&Opl, g_Opl);
    cudaGetSymbolAddress((void**)&Wqkvh, g_Wqkvh);
    cudaGetSymbolAddress((void**)&Wqkvl, g_Wqkvl);
    cudaGetSymbolAddress((void**)&Wph_, g_Wph);
    cudaGetSymbolAddress((void**)&Wpl_, g_Wpl);
    cudaGetSymbolAddress((void**)&Woh, g_Woh);
    cudaGetSymbolAddress((void**)&Wol, g_Wol);

    cudaFuncSetAttribute((const void*)bf16_gemm<0, 0>, cudaFuncAttributeMaxDynamicSharedMemorySize, G2_SMEM);
    cudaFuncSetAttribute((const void*)bf16_gemm<0, 1>, cudaFuncAttributeMaxDynamicSharedMemorySize, G2_SMEM);
    cudaFuncSetAttribute((const void*)bf16_gemm<1, 3>, cudaFuncAttributeMaxDynamicSharedMemorySize, G2_SMEM);
    cudaFuncSetAttribute((const void*)flash_attn, cudaFuncAttributeMaxDynamicSharedMemorySize, FL_SMEM);

    dim3 blk(256);

    // 1) all independent packs
    megapack1<<<dim3(4096, 1, 8), blk>>>(
        x, pos, mask, Wq, Wk, Wv, Wp, Wo,
        Wqkvh, Wqkvl, Wph_, Wpl_, Woh, Wol, xph, xpl, pph, ppl, Mb);

    // 2) fused Q/K/V/P projection (grid.z = 4):
    //    h==0: fp32 Q + QR pack; h==1: packed K; h==2: transposed fp16 V; h==3: packed P
    bf16_gemm<0, 1><<<dim3(8, 32, 4), blk, G2_SMEM>>>(
        xph, xpl, 256, 0, 0,
        Wqkvh, Wqkvl, 512, 0, 131072,
        QKV, DM, 0, 2097152,
        NB * TT, DM, 256, bq, bk, bv, Kph, Kpl, pbv, QRh, QRl, VTh,
        pph, ppl, Wph_, Wpl_, bp, Pph, Ppl);

    // 3) R = (Q[512:]+pbv) @ P^T per (b,h), fp16 output
    bf16_gemm<1, 3><<<dim3(32, 4, 32), blk, G2_SMEM>>>(
        QRh, QRl, 32, 8LL * 512 * 32, 512 * 32,
        Pph, Ppl, 256, 0, 32,
        (float*)Rh, RSTR, 8LL * 512 * RSTR, (ll)512 * RSTR,
        512, LL, 32, nullptr, nullptr, nullptr, nullptr, nullptr, nullptr, nullptr, nullptr, nullptr,
        nullptr, nullptr, nullptr, nullptr, nullptr, nullptr, nullptr);

    // 4) flash attention (fp16 R)
    flash_attn<<<dim3(16, 32), dim3(128), FL_SMEM>>>(
        QKV, Kph, Kpl, VTh, pbu, Rh, Mb, Oph, Opl);

    // 5) out = O @ Wo + bo
    bf16_gemm<0, 0><<<dim3(8, 32, 1), blk, G2_SMEM>>>(
        Oph, Opl, 256, 0, 0, Woh, Wol, 512, 0, 0,
        out, DM, 0, 0, NB * TT, DM, 256, bo, bo, bo, nullptr, nullptr, nullptr, nullptr, nullptr, nullptr,
        nullptr, nullptr, nullptr, nullptr, nullptr, nullptr, nullptr);
}